// round 13
// baseline (speedup 1.0000x reference)
#include <cuda_runtime.h>
#include <cuda_fp16.h>
#include <math.h>

typedef unsigned long long u64;
typedef unsigned int u32;
typedef unsigned short u16;

#define BB   32
#define CC   128
#define ICC  256
#define HWD  4096
#define HIDD 512

#define HSCALE 256.0f
#define HINV   (1.0f / 256.0f)

// ---------------- scratch (static __device__, no allocation) ----------------
__device__ float g_kb[ICC];                    // BN1 bias folded through k
__device__ float g_inv2[CC], g_beta2[CC];      // BN2 folded params
__device__ float g_rowmax[BB * ICC], g_rowsum[BB * ICC];
__device__ float g_h[(size_t)BB * ICC * HWD];  // gemm1 out (pre-softmax), fp32
__device__ float g_xr[(size_t)BB * CC * HWD];  // residual x + attn, fp32

// packed fp16 activation banks, channel-last: one u32 per 2 channels
__device__ __align__(16) u32 g_xs[(size_t)BB * HWD * (CC / 2)];
__device__ __align__(16) u32 g_hs[(size_t)BB * HWD * (ICC / 2)];
__device__ __align__(16) u32 g_nx[(size_t)BB * HWD * (CC / 2)];
__device__ __align__(16) u32 g_tx[(size_t)BB * HWD * (HIDD / 2)];

// fp16 hi/lo split weight planes (A operands)
__device__ __align__(16) u16 g_kA_h[ICC * CC],     g_kA_l[ICC * CC];
__device__ __align__(16) u16 g_vA_h[CC * ICC],     g_vA_l[CC * ICC];
__device__ __align__(16) u16 g_w1h[HIDD * CC * 9], g_w1l[HIDD * CC * 9];
__device__ __align__(16) u16 g_w2h[CC * HIDD * 9], g_w2l[CC * HIDD * 9];

// ---------------- helpers ----------------------------------------------------
__device__ __forceinline__ u16 f16b(float v) {
    return __half_as_ushort(__float2half_rn(v));
}
__device__ __forceinline__ void split_f16(float v, u16& h, u16& l) {
    __half hh = __float2half_rn(v);
    h = __half_as_ushort(hh);
    l = __half_as_ushort(__float2half_rn(v - __half2float(hh)));
}
__device__ __forceinline__ u32 pack2_f16(float v0, float v1) {
    return (u32)f16b(v0) | ((u32)f16b(v1) << 16);
}
__device__ __forceinline__ void mma16816(float& c0, float& c1, float& c2, float& c3,
                                         u32 a0, u32 a1, u32 a2, u32 a3,
                                         u32 b0, u32 b1) {
    asm volatile(
        "mma.sync.aligned.m16n8k16.row.col.f32.f16.f16.f32 "
        "{%0,%1,%2,%3},{%4,%5,%6,%7},{%8,%9},{%0,%1,%2,%3};"
        : "+f"(c0), "+f"(c1), "+f"(c2), "+f"(c3)
        : "r"(a0), "r"(a1), "r"(a2), "r"(a3), "r"(b0), "r"(b1));
}
__device__ __forceinline__ void ldmatrix4(u32* r, u32 saddr) {
    asm volatile(
        "ldmatrix.sync.aligned.m8n8.x4.shared.b16 {%0,%1,%2,%3}, [%4];"
        : "=r"(r[0]), "=r"(r[1]), "=r"(r[2]), "=r"(r[3]) : "r"(saddr));
}
__device__ __forceinline__ u32 smem_u32(const void* p) {
    u32 a;
    asm("{ .reg .u64 t; cvta.to.shared.u64 t, %1; cvt.u32.u64 %0, t; }"
        : "=r"(a) : "l"(p));
    return a;
}
__device__ __forceinline__ float gelu_exact(float v) {
    return 0.5f * v * (1.0f + erff(v * 0.70710678118654752f));
}
// interleave permutation within each 8-word k-group: [0,4,1,5,2,6,3,7]
__device__ __forceinline__ int kperm(int kp) {
    int t7 = kp & 7;
    return (kp & ~7) + ((t7 < 4) ? (2 * t7) : (2 * (t7 - 4) + 1));
}

// ---------------- K0: fold BN1 into k (split fp16), BN2 params --------------
__global__ void k_fold(const float* __restrict__ bn1_g, const float* __restrict__ bn1_b,
                       const float* __restrict__ bn1_m, const float* __restrict__ bn1_v,
                       const float* __restrict__ kmat,
                       const float* __restrict__ bn2_g, const float* __restrict__ bn2_b,
                       const float* __restrict__ bn2_m, const float* __restrict__ bn2_v) {
    __shared__ float inv1[CC], beta1[CC];
    int t = threadIdx.x;
    if (t < CC) {
        float iv = bn1_g[t] * rsqrtf(bn1_v[t] + 1e-5f);
        inv1[t] = iv;
        beta1[t] = bn1_b[t] - bn1_m[t] * iv;
        float iv2 = bn2_g[t] * rsqrtf(bn2_v[t] + 1e-6f);
        g_inv2[t] = iv2;
        g_beta2[t] = bn2_b[t] - bn2_m[t] * iv2;
    }
    __syncthreads();
    int o = t;  // 0..255
    float s = 0.f;
    for (int c = 0; c < CC; ++c) {
        float kv = kmat[o * CC + c];
        u16 h, l; split_f16(kv * inv1[c], h, l);
        g_kA_h[o * CC + c] = h;
        g_kA_l[o * CC + c] = l;
        s += kv * beta1[c];
    }
    g_kb[o] = s;
}

// ------- K0b: split + reorder conv weights to [oc][tap*IC+ic]; split v ------
__global__ void k_prep_w(const float* __restrict__ w1, const float* __restrict__ w2,
                         const float* __restrict__ vmat) {
    const int n1 = HIDD * CC * 9;
    const int n2 = CC * HIDD * 9;
    const int n3 = CC * ICC;
    int stride = gridDim.x * blockDim.x;
    for (int i = blockIdx.x * blockDim.x + threadIdx.x; i < n1 + n2 + n3; i += stride) {
        u16 h, l;
        if (i < n1) {
            int oc = i / (CC * 9), rem = i - oc * (CC * 9);
            int ic = rem / 9, tap = rem - ic * 9;
            split_f16(w1[i], h, l);
            int j = oc * (CC * 9) + tap * CC + ic;
            g_w1h[j] = h; g_w1l[j] = l;
        } else if (i < n1 + n2) {
            int q = i - n1;
            int oc = q / (HIDD * 9), rem = q - oc * (HIDD * 9);
            int ic = rem / 9, tap = rem - ic * 9;
            split_f16(w2[q], h, l);
            int j = oc * (HIDD * 9) + tap * HIDD + ic;
            g_w2h[j] = h; g_w2l[j] = l;
        } else {
            int j = i - n1 - n2;
            split_f16(vmat[j], h, l);
            g_vA_h[j] = h; g_vA_l[j] = l;
        }
    }
}

// ------- K0c: x [b][c][s] fp32 -> g_xs [b][s][c/2] packed fp16 --------------
__global__ void k_xsplit(const float* __restrict__ x) {
    __shared__ float sm[CC * 65];   // [c][65] pad
    int s0 = blockIdx.x * 64, b = blockIdx.y;
    int tid = threadIdx.x;
    for (int i = tid; i < CC * 64; i += 256) {
        int c = i >> 6, n = i & 63;
        sm[c * 65 + n] = x[((size_t)b * CC + c) * HWD + s0 + n];
    }
    __syncthreads();
    for (int i = tid; i < 64 * 64; i += 256) {
        int n = i >> 6, cp = i & 63;
        float v0 = sm[(2 * cp) * 65 + n];
        float v1 = sm[(2 * cp + 1) * 65 + n];
        g_xs[((size_t)b * HWD + s0 + n) * 64 + cp] = pack2_f16(v0, v1);
    }
}

// ---------------- 1x1 GEMMs via mma (fp16, A-split, pipelined) --------------
template <int MODE>
__global__ void __launch_bounds__(256) k_gemm_mma(const float* __restrict__ x) {
    constexpr int K   = (MODE == 0) ? CC : ICC;
    constexpr int KP  = K / 2;
    constexpr int KPs = (MODE == 0) ? 72 : 136;   // pad: stride % 32 == 8
    constexpr int KS  = K / 16;
    extern __shared__ char smraw[];
    u32* sB = (u32*)smraw;                        // [64][KPs], k-interleaved

    const u16* Ah = (MODE == 0) ? g_kA_h : g_vA_h;
    const u16* Al = (MODE == 0) ? g_kA_l : g_vA_l;
    const u32* src = (MODE == 0) ? g_xs : g_hs;

    int s0 = blockIdx.x * 64, oc0 = blockIdx.y * 128, b = blockIdx.z;
    int tid = threadIdx.x;
    int w = tid >> 5, lane = tid & 31;
    int g = lane >> 2, t = lane & 3;

    float acc[8][4];
#pragma unroll
    for (int nt = 0; nt < 8; ++nt)
#pragma unroll
        for (int q = 0; q < 4; ++q) acc[nt][q] = 0.f;

    for (int i = tid; i < 64 * KP; i += 256) {
        int n = (MODE == 0) ? (i >> 6) : (i >> 7);
        int kp = (MODE == 0) ? (i & 63) : (i & 127);
        sB[n * KPs + kperm(kp)] = src[((size_t)b * HWD + s0 + n) * KP + kp];
    }
    __syncthreads();

    int rowA = oc0 + w * 16 + g;
    const u16* pAh = Ah + (size_t)rowA * K;
    const u16* pAl = Al + (size_t)rowA * K;

    u32 cah[4], cal[4], nah[4], nal[4];
    {
        int kc = t * 2;
        cah[0] = *(const u32*)(pAh + kc);
        cah[1] = *(const u32*)(pAh + (size_t)8 * K + kc);
        cah[2] = *(const u32*)(pAh + kc + 8);
        cah[3] = *(const u32*)(pAh + (size_t)8 * K + kc + 8);
        cal[0] = *(const u32*)(pAl + kc);
        cal[1] = *(const u32*)(pAl + (size_t)8 * K + kc);
        cal[2] = *(const u32*)(pAl + kc + 8);
        cal[3] = *(const u32*)(pAl + (size_t)8 * K + kc + 8);
    }

#pragma unroll
    for (int ks = 0; ks < KS; ++ks) {
        if (ks + 1 < KS) {
            int kc = (ks + 1) * 16 + t * 2;
            nah[0] = *(const u32*)(pAh + kc);
            nah[1] = *(const u32*)(pAh + (size_t)8 * K + kc);
            nah[2] = *(const u32*)(pAh + kc + 8);
            nah[3] = *(const u32*)(pAh + (size_t)8 * K + kc + 8);
            nal[0] = *(const u32*)(pAl + kc);
            nal[1] = *(const u32*)(pAl + (size_t)8 * K + kc);
            nal[2] = *(const u32*)(pAl + kc + 8);
            nal[3] = *(const u32*)(pAl + (size_t)8 * K + kc + 8);
        }
        int kw = ks * 8 + 2 * t;
#pragma unroll
        for (int nt = 0; nt < 8; ++nt) {
            u64 B01 = *(const u64*)&sB[(nt * 8 + g) * KPs + kw];
            u32 b0 = (u32)B01, b1 = (u32)(B01 >> 32);
            mma16816(acc[nt][0], acc[nt][1], acc[nt][2], acc[nt][3],
                     cah[0], cah[1], cah[2], cah[3], b0, b1);
            mma16816(acc[nt][0], acc[nt][1], acc[nt][2], acc[nt][3],
                     cal[0], cal[1], cal[2], cal[3], b0, b1);
        }
#pragma unroll
        for (int q = 0; q < 4; ++q) { cah[q] = nah[q]; cal[q] = nal[q]; }
    }

    if (MODE == 0) {
#pragma unroll
        for (int nt = 0; nt < 8; ++nt) {
            int px = s0 + nt * 8 + t * 2;
            int r0 = rowA, r1 = rowA + 8;
            float k0 = g_kb[r0], k1 = g_kb[r1];
            size_t i0 = ((size_t)b * ICC + r0) * HWD + px;
            size_t i1 = ((size_t)b * ICC + r1) * HWD + px;
            *(float2*)(g_h + i0) = make_float2(acc[nt][0] + k0, acc[nt][1] + k0);
            *(float2*)(g_h + i1) = make_float2(acc[nt][2] + k1, acc[nt][3] + k1);
        }
    } else {
        __syncthreads();                       // done reading sB
        u16* th = (u16*)smraw;                 // [px][128]
        int r0 = rowA, r1 = rowA + 8;
        float iv0 = g_inv2[r0], be0 = g_beta2[r0];
        float iv1 = g_inv2[r1], be1 = g_beta2[r1];
#pragma unroll
        for (int nt = 0; nt < 8; ++nt) {
            int pxl = nt * 8 + t * 2;
            size_t i0 = ((size_t)b * CC + r0) * HWD + s0 + pxl;
            size_t i1 = ((size_t)b * CC + r1) * HWD + s0 + pxl;
            float2 x0 = *(const float2*)(x + i0);
            float2 x1 = *(const float2*)(x + i1);
            float xr00 = acc[nt][0] * HINV + x0.x, xr01 = acc[nt][1] * HINV + x0.y;
            float xr10 = acc[nt][2] * HINV + x1.x, xr11 = acc[nt][3] * HINV + x1.y;
            *(float2*)(g_xr + i0) = make_float2(xr00, xr01);
            *(float2*)(g_xr + i1) = make_float2(xr10, xr11);
            th[pxl * 128 + r0] = f16b(xr00 * iv0 + be0);
            th[(pxl + 1) * 128 + r0] = f16b(xr01 * iv0 + be0);
            th[pxl * 128 + r1] = f16b(xr10 * iv1 + be1);
            th[(pxl + 1) * 128 + r1] = f16b(xr11 * iv1 + be1);
        }
        __syncthreads();
        const u32* th32 = (const u32*)th;
        for (int i = tid; i < 64 * 64; i += 256) {
            int px = i >> 6, cp = i & 63;
            g_nx[((size_t)b * HWD + s0 + px) * 64 + cp] = th32[px * 64 + cp];
        }
    }
}

// ---------------- K2: per-row (b,o) max & sum of exp over 4096 spatial ------
__global__ void k_rowstats() {
    int r = blockIdx.x;
    const float4* p = (const float4*)(g_h + (size_t)r * HWD);
    int t = threadIdx.x;
    float v[16];
#pragma unroll
    for (int k = 0; k < 4; ++k) {
        float4 f = p[t + k * 256];
        v[k * 4 + 0] = f.x; v[k * 4 + 1] = f.y; v[k * 4 + 2] = f.z; v[k * 4 + 3] = f.w;
    }
    float m = v[0];
#pragma unroll
    for (int i = 1; i < 16; ++i) m = fmaxf(m, v[i]);
    __shared__ float red[256];
    red[t] = m; __syncthreads();
    for (int off = 128; off > 0; off >>= 1) {
        if (t < off) red[t] = fmaxf(red[t], red[t + off]);
        __syncthreads();
    }
    float rmax = red[0];
    __syncthreads();
    float s = 0.f;
#pragma unroll
    for (int i = 0; i < 16; ++i) s += __expf(v[i] - rmax);
    red[t] = s; __syncthreads();
    for (int off = 128; off > 0; off >>= 1) {
        if (t < off) red[t] += red[t + off];
        __syncthreads();
    }
    if (t == 0) { g_rowmax[r] = rmax; g_rowsum[r] = red[0]; }
}

// --- K3: softmax + per-head channel-sum norm; write packed fp16 (x256) ------
__global__ void k_dnorm() {
    int s = blockIdx.x * 256 + threadIdx.x;
    int nh = blockIdx.y, b = blockIdx.z;
    __shared__ float smax[32], sinv[32];
    if (threadIdx.x < 32) {
        int rr = b * ICC + nh * 32 + threadIdx.x;
        smax[threadIdx.x] = g_rowmax[rr];
        sinv[threadIdx.x] = 1.0f / g_rowsum[rr];
    }
    __syncthreads();
    float e[32];
    float d = 0.f;
    const float* base = g_h + ((size_t)b * ICC + nh * 32) * HWD + s;
#pragma unroll
    for (int c = 0; c < 32; ++c) {
        float val = __expf(base[(size_t)c * HWD] - smax[c]) * sinv[c];
        e[c] = val; d += val;
    }
    float w = HSCALE / (d + 1e-6f);
    u32* dst = g_hs + ((size_t)b * HWD + s) * (ICC / 2) + nh * 16;
#pragma unroll
    for (int c = 0; c < 32; c += 2)
        dst[c >> 1] = pack2_f16(e[c] * w, e[c + 1] * w);
}

// ---------------- 3x3 conv: smem weights + ldmatrix A + 128-px tiles --------
// Block: (y-pair, 128-oc group, b). M=128 oc, N=128 px (2 rows), K=ic*9.
// Per 16-channel chunk: stage weight slab (hi+lo) + im2col acts into smem.
// MODE 0: B from g_nx -> bias + GELU -> pack fp16 -> g_tx (channel-last)
// MODE 1: B from g_tx -> bias + g_xr residual -> dout fp32 NCHW
#define WSTR 152                                // halfwords per oc row (pad)
#define CBN  128                                // pixels per block
#define CBW  72                                 // u32 words per px row in sB
#define CONV_SMEM (128 * WSTR * 2 * 2 + CBN * CBW * 4)   // 77824+36864=114688

template <int MODE>
__global__ void __launch_bounds__(256) k_conv_mma(const float* __restrict__ bias,
                                                  float* __restrict__ dout) {
    constexpr int ICT  = (MODE == 0) ? 128 : 512;
    constexpr int Kt   = ICT * 9;
    constexpr int KPIC = ICT / 2;
    const u32* srcB = (MODE == 0) ? g_nx : g_tx;
    const u16* Wh = (MODE == 0) ? g_w1h : g_w2h;
    const u16* Wl = (MODE == 0) ? g_w1l : g_w2l;

    extern __shared__ char smraw[];
    u16* sWh = (u16*)smraw;                    // [128][WSTR]
    u16* sWl = sWh + 128 * WSTR;
    u32* sB  = (u32*)(smraw + 128 * WSTR * 4); // [128][CBW] k-interleaved

    int y0 = blockIdx.x * 2, oc0 = blockIdx.y * 128, b = blockIdx.z;
    int tid = threadIdx.x;
    int w = tid >> 5, lane = tid & 31;
    int g = lane >> 2, t = lane & 3;

    float acc[16][4];
#pragma unroll
    for (int nt = 0; nt < 16; ++nt)
#pragma unroll
        for (int q = 0; q < 4; ++q) acc[nt][q] = 0.f;

    // ldmatrix lane addressing: lanes 0-15 -> rows 0-15 col 0; 16-31 -> col 8
    int rowl = lane & 15, colo = (lane >> 4) * 8;
    u32 aoff_h = smem_u32(sWh) + (u32)(((w * 16 + rowl) * WSTR + colo) * 2);
    u32 aoff_l = aoff_h + 128 * WSTR * 2;

    const u32* inb = srcB + (size_t)b * HWD * KPIC;
    const u16* gWh = Wh + (size_t)oc0 * Kt;
    const u16* gWl = Wl + (size_t)oc0 * Kt;

    for (int ci = 0; ci < ICT / 16; ++ci) {
        // stage weights: uint4 copies, [oc][tap][16 ic] -> sW[oc][tap*16..]
        for (int j = tid; j < 128 * 9 * 2; j += 256) {
            int oc = j / 18, r = j - oc * 18, tap = r >> 1, half = r & 1;
            size_t go = (size_t)oc * Kt + tap * ICT + ci * 16 + half * 8;
            int so = oc * WSTR + tap * 16 + half * 8;
            *(uint4*)(sWh + so) = *(const uint4*)(gWh + go);
            *(uint4*)(sWl + so) = *(const uint4*)(gWl + go);
        }
        // stage acts: one u32 per (n, tap, icp), k-group interleaved
        for (int i = tid; i < CBN * CBW; i += 256) {
            int n = i / CBW, r = i - n * CBW;
            int tap = r >> 3, icp = r & 7;
            int dy = tap / 3, dx = tap - dy * 3;
            int yy = y0 + (n >> 6) + dy - 1;
            int xx = (n & 63) + dx - 1;
            u32 val = 0;
            if ((unsigned)xx < 64u && (unsigned)yy < 64u)
                val = inb[(size_t)(yy * 64 + xx) * KPIC + ci * 8 + icp];
            int pos = (tap << 3) + ((icp < 4) ? (2 * icp) : (2 * (icp - 4) + 1));
            sB[n * CBW + pos] = val;
        }
        __syncthreads();

        u32 cah[4], cal[4], nah[4], nal[4];
        ldmatrix4(cah, aoff_h);
        ldmatrix4(cal, aoff_l);
#pragma unroll
        for (int ks = 0; ks < 9; ++ks) {
            if (ks + 1 < 9) {
                ldmatrix4(nah, aoff_h + (ks + 1) * 32);
                ldmatrix4(nal, aoff_l + (ks + 1) * 32);
            }
            int kw = ks * 8 + 2 * t;
#pragma unroll
            for (int nt = 0; nt < 16; ++nt) {
                u64 B01 = *(const u64*)&sB[(nt * 8 + g) * CBW + kw];
                u32 b0 = (u32)B01, b1 = (u32)(B01 >> 32);
                mma16816(acc[nt][0], acc[nt][1], acc[nt][2], acc[nt][3],
                         cah[0], cah[1], cah[2], cah[3], b0, b1);
                mma16816(acc[nt][0], acc[nt][1], acc[nt][2], acc[nt][3],
                         cal[0], cal[1], cal[2], cal[3], b0, b1);
            }
#pragma unroll
            for (int q = 0; q < 4; ++q) { cah[q] = nah[q]; cal[q] = nal[q]; }
        }
        __syncthreads();
    }

    int r0 = oc0 + w * 16 + g, r1 = r0 + 8;
    float b0v = bias[r0], b1v = bias[r1];

    if (MODE == 0) {
        // GELU -> pack fp16 -> smem transpose -> channel-last g_tx
        u16* th = (u16*)smraw;                 // [128 px][128 oc-local]
        int lr0 = r0 - oc0, lr1 = r1 - oc0;
#pragma unroll
        for (int nt = 0; nt < 16; ++nt) {
            int pxl = nt * 8 + t * 2;
            th[pxl * 128 + lr0] = f16b(gelu_exact(acc[nt][0] + b0v));
            th[(pxl + 1) * 128 + lr0] = f16b(gelu_exact(acc[nt][1] + b0v));
            th[pxl * 128 + lr1] = f16b(gelu_exact(acc[nt][2] + b1v));
            th[(pxl + 1) * 128 + lr1] = f16b(gelu_exact(acc[nt][3] + b1v));
        }
        __syncthreads();
        const u32* th32 = (const u32*)th;
        for (int i = tid; i < 128 * 64; i += 256) {
            int px = i >> 6, cp = i & 63;
            g_tx[((size_t)b * HWD + y0 * 64 + px) * (HIDD / 2) + oc0 / 2 + cp] =
                th32[px * 64 + cp];
        }
    } else {
#pragma unroll
        for (int nt = 0; nt < 16; ++nt) {
            int px = nt * 8 + t * 2;
            int s = y0 * 64 + px;
            size_t i0 = ((size_t)b * CC + r0) * HWD + s;
            size_t i1 = ((size_t)b * CC + r1) * HWD + s;
            float2 x0 = *(const float2*)(g_xr + i0);
            float2 x1 = *(const float2*)(g_xr + i1);
            *(float2*)(dout + i0) = make_float2(acc[nt][0] + b0v + x0.x,
                                                acc[nt][1] + b0v + x0.y);
            *(float2*)(dout + i1) = make_float2(acc[nt][2] + b1v + x1.x,
                                                acc[nt][3] + b1v + x1.y);
        }
    }
}

// ---------------------------------------------------------------------------
extern "C" void kernel_launch(void* const* d_in, const int* in_sizes, int n_in,
                              void* d_out, int out_size) {
    (void)in_sizes; (void)n_in; (void)out_size;
    const float* x     = (const float*)d_in[0];
    const float* bn1_g = (const float*)d_in[1];
    const float* bn1_b = (const float*)d_in[2];
    const float* bn1_m = (const float*)d_in[3];
    const float* bn1_v = (const float*)d_in[4];
    const float* kmat  = (const float*)d_in[5];
    const float* vmat  = (const float*)d_in[6];
    const float* bn2_g = (const float*)d_in[7];
    const float* bn2_b = (const float*)d_in[8];
    const float* bn2_m = (const float*)d_in[9];
    const float* bn2_v = (const float*)d_in[10];
    const float* w1    = (const float*)d_in[11];
    const float* b1    = (const float*)d_in[12];
    const float* w2    = (const float*)d_in[13];
    const float* b2    = (const float*)d_in[14];
    float* out = (float*)d_out;

    const int GEMM0_SMEM = 64 * 72 * 4;    // 18432
    const int GEMM1_SMEM = 64 * 136 * 4;   // 34816

    static bool attr_done = false;
    if (!attr_done) {
        cudaFuncSetAttribute(k_conv_mma<0>, cudaFuncAttributeMaxDynamicSharedMemorySize, CONV_SMEM);
        cudaFuncSetAttribute(k_conv_mma<1>, cudaFuncAttributeMaxDynamicSharedMemorySize, CONV_SMEM);
        attr_done = true;
    }

    k_fold<<<1, 256>>>(bn1_g, bn1_b, bn1_m, bn1_v, kmat,
                       bn2_g, bn2_b, bn2_m, bn2_v);
    k_prep_w<<<512, 256>>>(w1, w2, vmat);

    dim3 gx(HWD / 64, BB);
    k_xsplit<<<gx, 256>>>(x);

    dim3 g1(HWD / 64, ICC / 128, BB);
    k_gemm_mma<0><<<g1, 256, GEMM0_SMEM>>>(x);

    k_rowstats<<<BB * ICC, 256>>>();

    dim3 gd(HWD / 256, 8, BB);
    k_dnorm<<<gd, 256>>>();

    dim3 g2(HWD / 64, CC / 128, BB);
    k_gemm_mma<1><<<g2, 256, GEMM1_SMEM>>>(x);

    dim3 gc1(32, HIDD / 128, BB);
    k_conv_mma<0><<<gc1, 256, CONV_SMEM>>>(b1, nullptr);

    dim3 gc2(32, CC / 128, BB);
    k_conv_mma<1><<<gc2, 256, CONV_SMEM>>>(b2, out);
}

// round 14
// speedup vs baseline: 1.5172x; 1.5172x over previous
#include <cuda_runtime.h>
#include <cuda_fp16.h>
#include <math.h>

typedef unsigned long long u64;
typedef unsigned int u32;
typedef unsigned short u16;

#define BB   32
#define CC   128
#define ICC  256
#define HWD  4096
#define HIDD 512

#define HSCALE 256.0f
#define HINV   (1.0f / 256.0f)

// ---------------- scratch (static __device__, no allocation) ----------------
__device__ float g_kb[ICC];                    // BN1 bias folded through k
__device__ float g_inv2[CC], g_beta2[CC];      // BN2 folded params
__device__ float g_rowmax[BB * ICC], g_rowsum[BB * ICC];
__device__ float g_h[(size_t)BB * ICC * HWD];  // gemm1 out (pre-softmax), fp32
__device__ float g_xr[(size_t)BB * CC * HWD];  // residual x + attn, fp32

// packed fp16 activation banks, channel-last: one u32 per 2 channels
__device__ __align__(16) u32 g_xs[(size_t)BB * HWD * (CC / 2)];
__device__ __align__(16) u32 g_hs[(size_t)BB * HWD * (ICC / 2)];
__device__ __align__(16) u32 g_nx[(size_t)BB * HWD * (CC / 2)];
__device__ __align__(16) u32 g_tx[(size_t)BB * HWD * (HIDD / 2)];

// fp16 weight planes. GEMM A operands keep hi/lo split; conv weights single.
__device__ __align__(16) u16 g_kA_h[ICC * CC],     g_kA_l[ICC * CC];
__device__ __align__(16) u16 g_vA_h[CC * ICC],     g_vA_l[CC * ICC];
__device__ __align__(16) u16 g_w1h[HIDD * CC * 9];   // [oc][tap*128+ic]
__device__ __align__(16) u16 g_w2h[CC * HIDD * 9];   // [oc][tap*512+ic]

// ---------------- helpers ----------------------------------------------------
__device__ __forceinline__ u16 f16b(float v) {
    return __half_as_ushort(__float2half_rn(v));
}
__device__ __forceinline__ void split_f16(float v, u16& h, u16& l) {
    __half hh = __float2half_rn(v);
    h = __half_as_ushort(hh);
    l = __half_as_ushort(__float2half_rn(v - __half2float(hh)));
}
__device__ __forceinline__ u32 pack2_f16(float v0, float v1) {
    return (u32)f16b(v0) | ((u32)f16b(v1) << 16);
}
__device__ __forceinline__ void mma16816(float& c0, float& c1, float& c2, float& c3,
                                         u32 a0, u32 a1, u32 a2, u32 a3,
                                         u32 b0, u32 b1) {
    asm volatile(
        "mma.sync.aligned.m16n8k16.row.col.f32.f16.f16.f32 "
        "{%0,%1,%2,%3},{%4,%5,%6,%7},{%8,%9},{%0,%1,%2,%3};"
        : "+f"(c0), "+f"(c1), "+f"(c2), "+f"(c3)
        : "r"(a0), "r"(a1), "r"(a2), "r"(a3), "r"(b0), "r"(b1));
}
__device__ __forceinline__ void ldmatrix4(u32* r, u32 saddr) {
    asm volatile(
        "ldmatrix.sync.aligned.m8n8.x4.shared.b16 {%0,%1,%2,%3}, [%4];"
        : "=r"(r[0]), "=r"(r[1]), "=r"(r[2]), "=r"(r[3]) : "r"(saddr));
}
__device__ __forceinline__ u32 smem_u32(const void* p) {
    u32 a;
    asm("{ .reg .u64 t; cvta.to.shared.u64 t, %1; cvt.u32.u64 %0, t; }"
        : "=r"(a) : "l"(p));
    return a;
}
__device__ __forceinline__ float gelu_exact(float v) {
    return 0.5f * v * (1.0f + erff(v * 0.70710678118654752f));
}
// interleave permutation within each 8-word k-group: [0,4,1,5,2,6,3,7]
__device__ __forceinline__ int kperm(int kp) {
    int t7 = kp & 7;
    return (kp & ~7) + ((t7 < 4) ? (2 * t7) : (2 * (t7 - 4) + 1));
}

// ---------------- K0: fold BN1 into k (split fp16), BN2 params --------------
__global__ void k_fold(const float* __restrict__ bn1_g, const float* __restrict__ bn1_b,
                       const float* __restrict__ bn1_m, const float* __restrict__ bn1_v,
                       const float* __restrict__ kmat,
                       const float* __restrict__ bn2_g, const float* __restrict__ bn2_b,
                       const float* __restrict__ bn2_m, const float* __restrict__ bn2_v) {
    __shared__ float inv1[CC], beta1[CC];
    int t = threadIdx.x;
    if (t < CC) {
        float iv = bn1_g[t] * rsqrtf(bn1_v[t] + 1e-5f);
        inv1[t] = iv;
        beta1[t] = bn1_b[t] - bn1_m[t] * iv;
        float iv2 = bn2_g[t] * rsqrtf(bn2_v[t] + 1e-6f);
        g_inv2[t] = iv2;
        g_beta2[t] = bn2_b[t] - bn2_m[t] * iv2;
    }
    __syncthreads();
    int o = t;  // 0..255
    float s = 0.f;
    for (int c = 0; c < CC; ++c) {
        float kv = kmat[o * CC + c];
        u16 h, l; split_f16(kv * inv1[c], h, l);
        g_kA_h[o * CC + c] = h;
        g_kA_l[o * CC + c] = l;
        s += kv * beta1[c];
    }
    g_kb[o] = s;
}

// ------- K0b: reorder conv weights to [oc][tap*IC+ic] fp16; split v ---------
__global__ void k_prep_w(const float* __restrict__ w1, const float* __restrict__ w2,
                         const float* __restrict__ vmat) {
    const int n1 = HIDD * CC * 9;
    const int n2 = CC * HIDD * 9;
    const int n3 = CC * ICC;
    int stride = gridDim.x * blockDim.x;
    for (int i = blockIdx.x * blockDim.x + threadIdx.x; i < n1 + n2 + n3; i += stride) {
        if (i < n1) {
            int oc = i / (CC * 9), rem = i - oc * (CC * 9);
            int ic = rem / 9, tap = rem - ic * 9;
            g_w1h[oc * (CC * 9) + tap * CC + ic] = f16b(w1[i]);
        } else if (i < n1 + n2) {
            int q = i - n1;
            int oc = q / (HIDD * 9), rem = q - oc * (HIDD * 9);
            int ic = rem / 9, tap = rem - ic * 9;
            g_w2h[oc * (HIDD * 9) + tap * HIDD + ic] = f16b(w2[q]);
        } else {
            int j = i - n1 - n2;
            u16 h, l;
            split_f16(vmat[j], h, l);
            g_vA_h[j] = h; g_vA_l[j] = l;
        }
    }
}

// ------- K0c: x [b][c][s] fp32 -> g_xs [b][s][c/2] packed fp16 --------------
__global__ void k_xsplit(const float* __restrict__ x) {
    __shared__ float sm[CC * 65];   // [c][65] pad
    int s0 = blockIdx.x * 64, b = blockIdx.y;
    int tid = threadIdx.x;
    for (int i = tid; i < CC * 64; i += 256) {
        int c = i >> 6, n = i & 63;
        sm[c * 65 + n] = x[((size_t)b * CC + c) * HWD + s0 + n];
    }
    __syncthreads();
    for (int i = tid; i < 64 * 64; i += 256) {
        int n = i >> 6, cp = i & 63;
        float v0 = sm[(2 * cp) * 65 + n];
        float v1 = sm[(2 * cp + 1) * 65 + n];
        g_xs[((size_t)b * HWD + s0 + n) * 64 + cp] = pack2_f16(v0, v1);
    }
}

// ---------------- 1x1 GEMMs via mma (fp16, A-split, pipelined) --------------
template <int MODE>
__global__ void __launch_bounds__(256) k_gemm_mma(const float* __restrict__ x) {
    constexpr int K   = (MODE == 0) ? CC : ICC;
    constexpr int KP  = K / 2;
    constexpr int KPs = (MODE == 0) ? 72 : 136;   // pad: stride % 32 == 8
    constexpr int KS  = K / 16;
    extern __shared__ char smraw[];
    u32* sB = (u32*)smraw;                        // [64][KPs], k-interleaved

    const u16* Ah = (MODE == 0) ? g_kA_h : g_vA_h;
    const u16* Al = (MODE == 0) ? g_kA_l : g_vA_l;
    const u32* src = (MODE == 0) ? g_xs : g_hs;

    int s0 = blockIdx.x * 64, oc0 = blockIdx.y * 128, b = blockIdx.z;
    int tid = threadIdx.x;
    int w = tid >> 5, lane = tid & 31;
    int g = lane >> 2, t = lane & 3;

    float acc[8][4];
#pragma unroll
    for (int nt = 0; nt < 8; ++nt)
#pragma unroll
        for (int q = 0; q < 4; ++q) acc[nt][q] = 0.f;

    for (int i = tid; i < 64 * KP; i += 256) {
        int n = (MODE == 0) ? (i >> 6) : (i >> 7);
        int kp = (MODE == 0) ? (i & 63) : (i & 127);
        sB[n * KPs + kperm(kp)] = src[((size_t)b * HWD + s0 + n) * KP + kp];
    }
    __syncthreads();

    int rowA = oc0 + w * 16 + g;
    const u16* pAh = Ah + (size_t)rowA * K;
    const u16* pAl = Al + (size_t)rowA * K;

    u32 cah[4], cal[4], nah[4], nal[4];
    {
        int kc = t * 2;
        cah[0] = *(const u32*)(pAh + kc);
        cah[1] = *(const u32*)(pAh + (size_t)8 * K + kc);
        cah[2] = *(const u32*)(pAh + kc + 8);
        cah[3] = *(const u32*)(pAh + (size_t)8 * K + kc + 8);
        cal[0] = *(const u32*)(pAl + kc);
        cal[1] = *(const u32*)(pAl + (size_t)8 * K + kc);
        cal[2] = *(const u32*)(pAl + kc + 8);
        cal[3] = *(const u32*)(pAl + (size_t)8 * K + kc + 8);
    }

#pragma unroll
    for (int ks = 0; ks < KS; ++ks) {
        if (ks + 1 < KS) {
            int kc = (ks + 1) * 16 + t * 2;
            nah[0] = *(const u32*)(pAh + kc);
            nah[1] = *(const u32*)(pAh + (size_t)8 * K + kc);
            nah[2] = *(const u32*)(pAh + kc + 8);
            nah[3] = *(const u32*)(pAh + (size_t)8 * K + kc + 8);
            nal[0] = *(const u32*)(pAl + kc);
            nal[1] = *(const u32*)(pAl + (size_t)8 * K + kc);
            nal[2] = *(const u32*)(pAl + kc + 8);
            nal[3] = *(const u32*)(pAl + (size_t)8 * K + kc + 8);
        }
        int kw = ks * 8 + 2 * t;
#pragma unroll
        for (int nt = 0; nt < 8; ++nt) {
            u64 B01 = *(const u64*)&sB[(nt * 8 + g) * KPs + kw];
            u32 b0 = (u32)B01, b1 = (u32)(B01 >> 32);
            mma16816(acc[nt][0], acc[nt][1], acc[nt][2], acc[nt][3],
                     cah[0], cah[1], cah[2], cah[3], b0, b1);
            mma16816(acc[nt][0], acc[nt][1], acc[nt][2], acc[nt][3],
                     cal[0], cal[1], cal[2], cal[3], b0, b1);
        }
#pragma unroll
        for (int q = 0; q < 4; ++q) { cah[q] = nah[q]; cal[q] = nal[q]; }
    }

    if (MODE == 0) {
#pragma unroll
        for (int nt = 0; nt < 8; ++nt) {
            int px = s0 + nt * 8 + t * 2;
            int r0 = rowA, r1 = rowA + 8;
            float k0 = g_kb[r0], k1 = g_kb[r1];
            size_t i0 = ((size_t)b * ICC + r0) * HWD + px;
            size_t i1 = ((size_t)b * ICC + r1) * HWD + px;
            *(float2*)(g_h + i0) = make_float2(acc[nt][0] + k0, acc[nt][1] + k0);
            *(float2*)(g_h + i1) = make_float2(acc[nt][2] + k1, acc[nt][3] + k1);
        }
    } else {
        __syncthreads();                       // done reading sB
        u16* th = (u16*)smraw;                 // [px][128]
        int r0 = rowA, r1 = rowA + 8;
        float iv0 = g_inv2[r0], be0 = g_beta2[r0];
        float iv1 = g_inv2[r1], be1 = g_beta2[r1];
#pragma unroll
        for (int nt = 0; nt < 8; ++nt) {
            int pxl = nt * 8 + t * 2;
            size_t i0 = ((size_t)b * CC + r0) * HWD + s0 + pxl;
            size_t i1 = ((size_t)b * CC + r1) * HWD + s0 + pxl;
            float2 x0 = *(const float2*)(x + i0);
            float2 x1 = *(const float2*)(x + i1);
            float xr00 = acc[nt][0] * HINV + x0.x, xr01 = acc[nt][1] * HINV + x0.y;
            float xr10 = acc[nt][2] * HINV + x1.x, xr11 = acc[nt][3] * HINV + x1.y;
            *(float2*)(g_xr + i0) = make_float2(xr00, xr01);
            *(float2*)(g_xr + i1) = make_float2(xr10, xr11);
            th[pxl * 128 + r0] = f16b(xr00 * iv0 + be0);
            th[(pxl + 1) * 128 + r0] = f16b(xr01 * iv0 + be0);
            th[pxl * 128 + r1] = f16b(xr10 * iv1 + be1);
            th[(pxl + 1) * 128 + r1] = f16b(xr11 * iv1 + be1);
        }
        __syncthreads();
        const u32* th32 = (const u32*)th;
        for (int i = tid; i < 64 * 64; i += 256) {
            int px = i >> 6, cp = i & 63;
            g_nx[((size_t)b * HWD + s0 + px) * 64 + cp] = th32[px * 64 + cp];
        }
    }
}

// ---------------- K2: per-row (b,o) max & sum of exp over 4096 spatial ------
__global__ void k_rowstats() {
    int r = blockIdx.x;
    const float4* p = (const float4*)(g_h + (size_t)r * HWD);
    int t = threadIdx.x;
    float v[16];
#pragma unroll
    for (int k = 0; k < 4; ++k) {
        float4 f = p[t + k * 256];
        v[k * 4 + 0] = f.x; v[k * 4 + 1] = f.y; v[k * 4 + 2] = f.z; v[k * 4 + 3] = f.w;
    }
    float m = v[0];
#pragma unroll
    for (int i = 1; i < 16; ++i) m = fmaxf(m, v[i]);
    __shared__ float red[256];
    red[t] = m; __syncthreads();
    for (int off = 128; off > 0; off >>= 1) {
        if (t < off) red[t] = fmaxf(red[t], red[t + off]);
        __syncthreads();
    }
    float rmax = red[0];
    __syncthreads();
    float s = 0.f;
#pragma unroll
    for (int i = 0; i < 16; ++i) s += __expf(v[i] - rmax);
    red[t] = s; __syncthreads();
    for (int off = 128; off > 0; off >>= 1) {
        if (t < off) red[t] += red[t + off];
        __syncthreads();
    }
    if (t == 0) { g_rowmax[r] = rmax; g_rowsum[r] = red[0]; }
}

// --- K3: softmax + per-head channel-sum norm; write packed fp16 (x256) ------
__global__ void k_dnorm() {
    int s = blockIdx.x * 256 + threadIdx.x;
    int nh = blockIdx.y, b = blockIdx.z;
    __shared__ float smax[32], sinv[32];
    if (threadIdx.x < 32) {
        int rr = b * ICC + nh * 32 + threadIdx.x;
        smax[threadIdx.x] = g_rowmax[rr];
        sinv[threadIdx.x] = 1.0f / g_rowsum[rr];
    }
    __syncthreads();
    float e[32];
    float d = 0.f;
    const float* base = g_h + ((size_t)b * ICC + nh * 32) * HWD + s;
#pragma unroll
    for (int c = 0; c < 32; ++c) {
        float val = __expf(base[(size_t)c * HWD] - smax[c]) * sinv[c];
        e[c] = val; d += val;
    }
    float w = HSCALE / (d + 1e-6f);
    u32* dst = g_hs + ((size_t)b * HWD + s) * (ICC / 2) + nh * 16;
#pragma unroll
    for (int c = 0; c < 32; c += 2)
        dst[c >> 1] = pack2_f16(e[c] * w, e[c + 1] * w);
}

// ------- 3x3 conv: single-plane smem weights + ldmatrix + 128-px tiles ------
// Block: (y-pair, 128-oc group, b). M=128 oc, N=128 px (2 rows), K=ic*9.
// MODE 0: B from g_nx -> bias + GELU -> pack fp16 -> g_tx (channel-last)
// MODE 1: B from g_tx -> bias + g_xr residual -> dout fp32 NCHW
#define WSTR 152                                // halfwords per oc row (pad)
#define CBN  128                                // pixels per block
#define CBW  72                                 // u32 words per px row in sB
#define CONV_SMEM (128 * WSTR * 2 + CBN * CBW * 4)   // 38912+36864=75776

template <int MODE>
__global__ void __launch_bounds__(256) k_conv_mma(const float* __restrict__ bias,
                                                  float* __restrict__ dout) {
    constexpr int ICT  = (MODE == 0) ? 128 : 512;
    constexpr int Kt   = ICT * 9;
    constexpr int KPIC = ICT / 2;
    const u32* srcB = (MODE == 0) ? g_nx : g_tx;
    const u16* Wg = (MODE == 0) ? g_w1h : g_w2h;

    extern __shared__ char smraw[];
    u16* sW = (u16*)smraw;                     // [128][WSTR]
    u32* sB = (u32*)(smraw + 128 * WSTR * 2);  // [128][CBW] k-interleaved

    int y0 = blockIdx.x * 2, oc0 = blockIdx.y * 128, b = blockIdx.z;
    int tid = threadIdx.x;
    int w = tid >> 5, lane = tid & 31;
    int g = lane >> 2, t = lane & 3;

    float acc[16][4];
#pragma unroll
    for (int nt = 0; nt < 16; ++nt)
#pragma unroll
        for (int q = 0; q < 4; ++q) acc[nt][q] = 0.f;

    // ldmatrix lane addressing: lanes 0-15 -> rows 0-15 col 0; 16-31 -> col 8
    int rowl = lane & 15, colo = (lane >> 4) * 8;
    u32 aoff = smem_u32(sW) + (u32)(((w * 16 + rowl) * WSTR + colo) * 2);

    const u32* inb = srcB + (size_t)b * HWD * KPIC;
    const u16* gW = Wg + (size_t)oc0 * Kt;

    for (int ci = 0; ci < ICT / 16; ++ci) {
        // stage weights: uint4 copies, [oc][tap][16 ic] -> sW[oc][tap*16..]
        for (int j = tid; j < 128 * 9 * 2; j += 256) {
            int oc = j / 18, r = j - oc * 18, tap = r >> 1, half = r & 1;
            size_t go = (size_t)oc * Kt + tap * ICT + ci * 16 + half * 8;
            *(uint4*)(sW + oc * WSTR + tap * 16 + half * 8) =
                *(const uint4*)(gW + go);
        }
        // stage acts: one u32 per (n, tap, icp), k-group interleaved
        for (int i = tid; i < CBN * CBW; i += 256) {
            int n = i / CBW, r = i - n * CBW;
            int tap = r >> 3, icp = r & 7;
            int dy = tap / 3, dx = tap - dy * 3;
            int yy = y0 + (n >> 6) + dy - 1;
            int xx = (n & 63) + dx - 1;
            u32 val = 0;
            if ((unsigned)xx < 64u && (unsigned)yy < 64u)
                val = inb[(size_t)(yy * 64 + xx) * KPIC + ci * 8 + icp];
            int pos = (tap << 3) + ((icp < 4) ? (2 * icp) : (2 * (icp - 4) + 1));
            sB[n * CBW + pos] = val;
        }
        __syncthreads();

        u32 ca[4], na[4];
        ldmatrix4(ca, aoff);
#pragma unroll
        for (int ks = 0; ks < 9; ++ks) {
            if (ks + 1 < 9) ldmatrix4(na, aoff + (ks + 1) * 32);
            int kw = ks * 8 + 2 * t;
#pragma unroll
            for (int nt = 0; nt < 16; ++nt) {
                u64 B01 = *(const u64*)&sB[(nt * 8 + g) * CBW + kw];
                mma16816(acc[nt][0], acc[nt][1], acc[nt][2], acc[nt][3],
                         ca[0], ca[1], ca[2], ca[3],
                         (u32)B01, (u32)(B01 >> 32));
            }
#pragma unroll
            for (int q = 0; q < 4; ++q) ca[q] = na[q];
        }
        __syncthreads();
    }

    int r0 = oc0 + w * 16 + g, r1 = r0 + 8;
    float b0v = bias[r0], b1v = bias[r1];

    if (MODE == 0) {
        // GELU -> pack fp16 -> smem transpose -> channel-last g_tx
        u16* th = (u16*)smraw;                 // [128 px][128 oc-local]
        int lr0 = r0 - oc0, lr1 = r1 - oc0;
#pragma unroll
        for (int nt = 0; nt < 16; ++nt) {
            int pxl = nt * 8 + t * 2;
            th[pxl * 128 + lr0] = f16b(gelu_exact(acc[nt][0] + b0v));
            th[(pxl + 1) * 128 + lr0] = f16b(gelu_exact(acc[nt][1] + b0v));
            th[pxl * 128 + lr1] = f16b(gelu_exact(acc[nt][2] + b1v));
            th[(pxl + 1) * 128 + lr1] = f16b(gelu_exact(acc[nt][3] + b1v));
        }
        __syncthreads();
        const u32* th32 = (const u32*)th;
        for (int i = tid; i < 128 * 64; i += 256) {
            int px = i >> 6, cp = i & 63;
            g_tx[((size_t)b * HWD + y0 * 64 + px) * (HIDD / 2) + oc0 / 2 + cp] =
                th32[px * 64 + cp];
        }
    } else {
#pragma unroll
        for (int nt = 0; nt < 16; ++nt) {
            int px = nt * 8 + t * 2;
            int s = y0 * 64 + px;
            size_t i0 = ((size_t)b * CC + r0) * HWD + s;
            size_t i1 = ((size_t)b * CC + r1) * HWD + s;
            float2 x0 = *(const float2*)(g_xr + i0);
            float2 x1 = *(const float2*)(g_xr + i1);
            *(float2*)(dout + i0) = make_float2(acc[nt][0] + b0v + x0.x,
                                                acc[nt][1] + b0v + x0.y);
            *(float2*)(dout + i1) = make_float2(acc[nt][2] + b1v + x1.x,
                                                acc[nt][3] + b1v + x1.y);
        }
    }
}

// ---------------------------------------------------------------------------
extern "C" void kernel_launch(void* const* d_in, const int* in_sizes, int n_in,
                              void* d_out, int out_size) {
    (void)in_sizes; (void)n_in; (void)out_size;
    const float* x     = (const float*)d_in[0];
    const float* bn1_g = (const float*)d_in[1];
    const float* bn1_b = (const float*)d_in[2];
    const float* bn1_m = (const float*)d_in[3];
    const float* bn1_v = (const float*)d_in[4];
    const float* kmat  = (const float*)d_in[5];
    const float* vmat  = (const float*)d_in[6];
    const float* bn2_g = (const float*)d_in[7];
    const float* bn2_b = (const float*)d_in[8];
    const float* bn2_m = (const float*)d_in[9];
    const float* bn2_v = (const float*)d_in[10];
    const float* w1    = (const float*)d_in[11];
    const float* b1    = (const float*)d_in[12];
    const float* w2    = (const float*)d_in[13];
    const float* b2    = (const float*)d_in[14];
    float* out = (float*)d_out;

    const int GEMM0_SMEM = 64 * 72 * 4;    // 18432
    const int GEMM1_SMEM = 64 * 136 * 4;   // 34816

    static bool attr_done = false;
    if (!attr_done) {
        cudaFuncSetAttribute(k_conv_mma<0>, cudaFuncAttributeMaxDynamicSharedMemorySize, CONV_SMEM);
        cudaFuncSetAttribute(k_conv_mma<1>, cudaFuncAttributeMaxDynamicSharedMemorySize, CONV_SMEM);
        attr_done = true;
    }

    k_fold<<<1, 256>>>(bn1_g, bn1_b, bn1_m, bn1_v, kmat,
                       bn2_g, bn2_b, bn2_m, bn2_v);
    k_prep_w<<<512, 256>>>(w1, w2, vmat);

    dim3 gx(HWD / 64, BB);
    k_xsplit<<<gx, 256>>>(x);

    dim3 g1(HWD / 64, ICC / 128, BB);
    k_gemm_mma<0><<<g1, 256, GEMM0_SMEM>>>(x);

    k_rowstats<<<BB * ICC, 256>>>();

    dim3 gd(HWD / 256, 8, BB);
    k_dnorm<<<gd, 256>>>();

    dim3 g2(HWD / 64, CC / 128, BB);
    k_gemm_mma<1><<<g2, 256, GEMM1_SMEM>>>(x);

    dim3 gc1(32, HIDD / 128, BB);
    k_conv_mma<0><<<gc1, 256, CONV_SMEM>>>(b1, nullptr);

    dim3 gc2(32, CC / 128, BB);
    k_conv_mma<1><<<gc2, 256, CONV_SMEM>>>(b2, out);
}

// round 16
// speedup vs baseline: 1.8578x; 1.2245x over previous
#include <cuda_runtime.h>
#include <cuda_fp16.h>
#include <math.h>

typedef unsigned long long u64;
typedef unsigned int u32;
typedef unsigned short u16;

#define BB   32
#define CC   128
#define ICC  256
#define HWD  4096
#define HIDD 512

#define HSCALE 256.0f
#define HINV   (1.0f / 256.0f)

// ---------------- scratch (static __device__, no allocation) ----------------
__device__ float g_kb[ICC];                    // BN1 bias folded through k
__device__ float g_inv2[CC], g_beta2[CC];      // BN2 folded params
__device__ float g_rowmax[BB * ICC], g_rowsum[BB * ICC];
__device__ float g_h[(size_t)BB * ICC * HWD];  // gemm1 out (pre-softmax), fp32
__device__ float g_xr[(size_t)BB * CC * HWD];  // residual x + attn, fp32

// packed fp16 activation banks, channel-last: one u32 per 2 channels
__device__ __align__(16) u32 g_xs[(size_t)BB * HWD * (CC / 2)];
__device__ __align__(16) u32 g_hs[(size_t)BB * HWD * (ICC / 2)];
__device__ __align__(16) u32 g_nx[(size_t)BB * HWD * (CC / 2)];
__device__ __align__(16) u32 g_tx[(size_t)BB * HWD * (HIDD / 2)];

// fp16 weight planes. GEMM A operands keep hi/lo split; conv weights single.
__device__ __align__(16) u16 g_kA_h[ICC * CC],     g_kA_l[ICC * CC];
__device__ __align__(16) u16 g_vA_h[CC * ICC],     g_vA_l[CC * ICC];
__device__ __align__(16) u16 g_w1h[HIDD * CC * 9];   // [oc][tap*128+ic]
__device__ __align__(16) u16 g_w2h[CC * HIDD * 9];   // [oc][tap*512+ic]

// ---------------- helpers ----------------------------------------------------
__device__ __forceinline__ u16 f16b(float v) {
    return __half_as_ushort(__float2half_rn(v));
}
__device__ __forceinline__ void split_f16(float v, u16& h, u16& l) {
    __half hh = __float2half_rn(v);
    h = __half_as_ushort(hh);
    l = __half_as_ushort(__float2half_rn(v - __half2float(hh)));
}
__device__ __forceinline__ u32 pack2_f16(float v0, float v1) {
    return (u32)f16b(v0) | ((u32)f16b(v1) << 16);
}
__device__ __forceinline__ void mma16816(float& c0, float& c1, float& c2, float& c3,
                                         u32 a0, u32 a1, u32 a2, u32 a3,
                                         u32 b0, u32 b1) {
    asm volatile(
        "mma.sync.aligned.m16n8k16.row.col.f32.f16.f16.f32 "
        "{%0,%1,%2,%3},{%4,%5,%6,%7},{%8,%9},{%0,%1,%2,%3};"
        : "+f"(c0), "+f"(c1), "+f"(c2), "+f"(c3)
        : "r"(a0), "r"(a1), "r"(a2), "r"(a3), "r"(b0), "r"(b1));
}
__device__ __forceinline__ void ldmatrix4(u32* r, u32 saddr) {
    asm volatile(
        "ldmatrix.sync.aligned.m8n8.x4.shared.b16 {%0,%1,%2,%3}, [%4];"
        : "=r"(r[0]), "=r"(r[1]), "=r"(r[2]), "=r"(r[3]) : "r"(saddr));
}
__device__ __forceinline__ u32 smem_u32(const void* p) {
    u32 a;
    asm("{ .reg .u64 t; cvta.to.shared.u64 t, %1; cvt.u32.u64 %0, t; }"
        : "=r"(a) : "l"(p));
    return a;
}
__device__ __forceinline__ float gelu_exact(float v) {
    return 0.5f * v * (1.0f + erff(v * 0.70710678118654752f));
}
// interleave permutation within each 8-word k-group: [0,4,1,5,2,6,3,7]
__device__ __forceinline__ int kperm(int kp) {
    int t7 = kp & 7;
    return (kp & ~7) + ((t7 < 4) ? (2 * t7) : (2 * (t7 - 4) + 1));
}

// ---------------- K0: fold BN1 into k (split fp16), BN2 params --------------
__global__ void k_fold(const float* __restrict__ bn1_g, const float* __restrict__ bn1_b,
                       const float* __restrict__ bn1_m, const float* __restrict__ bn1_v,
                       const float* __restrict__ kmat,
                       const float* __restrict__ bn2_g, const float* __restrict__ bn2_b,
                       const float* __restrict__ bn2_m, const float* __restrict__ bn2_v) {
    __shared__ float inv1[CC], beta1[CC];
    int t = threadIdx.x;
    if (t < CC) {
        float iv = bn1_g[t] * rsqrtf(bn1_v[t] + 1e-5f);
        inv1[t] = iv;
        beta1[t] = bn1_b[t] - bn1_m[t] * iv;
        float iv2 = bn2_g[t] * rsqrtf(bn2_v[t] + 1e-6f);
        g_inv2[t] = iv2;
        g_beta2[t] = bn2_b[t] - bn2_m[t] * iv2;
    }
    __syncthreads();
    int o = t;  // 0..255
    float s = 0.f;
    for (int c = 0; c < CC; ++c) {
        float kv = kmat[o * CC + c];
        u16 h, l; split_f16(kv * inv1[c], h, l);
        g_kA_h[o * CC + c] = h;
        g_kA_l[o * CC + c] = l;
        s += kv * beta1[c];
    }
    g_kb[o] = s;
}

// ------- K0b: reorder conv weights to [oc][tap*IC+ic] fp16; split v ---------
__global__ void k_prep_w(const float* __restrict__ w1, const float* __restrict__ w2,
                         const float* __restrict__ vmat) {
    const int n1 = HIDD * CC * 9;
    const int n2 = CC * HIDD * 9;
    const int n3 = CC * ICC;
    int stride = gridDim.x * blockDim.x;
    for (int i = blockIdx.x * blockDim.x + threadIdx.x; i < n1 + n2 + n3; i += stride) {
        if (i < n1) {
            int oc = i / (CC * 9), rem = i - oc * (CC * 9);
            int ic = rem / 9, tap = rem - ic * 9;
            g_w1h[oc * (CC * 9) + tap * CC + ic] = f16b(w1[i]);
        } else if (i < n1 + n2) {
            int q = i - n1;
            int oc = q / (HIDD * 9), rem = q - oc * (HIDD * 9);
            int ic = rem / 9, tap = rem - ic * 9;
            g_w2h[oc * (HIDD * 9) + tap * HIDD + ic] = f16b(w2[q]);
        } else {
            int j = i - n1 - n2;
            u16 h, l;
            split_f16(vmat[j], h, l);
            g_vA_h[j] = h; g_vA_l[j] = l;
        }
    }
}

// ------- K0c: x [b][c][s] fp32 -> g_xs [b][s][c/2] packed fp16 --------------
__global__ void k_xsplit(const float* __restrict__ x) {
    __shared__ float sm[CC * 65];   // [c][65] pad
    int s0 = blockIdx.x * 64, b = blockIdx.y;
    int tid = threadIdx.x;
    for (int i = tid; i < CC * 64; i += 256) {
        int c = i >> 6, n = i & 63;
        sm[c * 65 + n] = x[((size_t)b * CC + c) * HWD + s0 + n];
    }
    __syncthreads();
    for (int i = tid; i < 64 * 64; i += 256) {
        int n = i >> 6, cp = i & 63;
        float v0 = sm[(2 * cp) * 65 + n];
        float v1 = sm[(2 * cp + 1) * 65 + n];
        g_xs[((size_t)b * HWD + s0 + n) * 64 + cp] = pack2_f16(v0, v1);
    }
}

// ---------------- 1x1 GEMMs via mma (fp16, A-split, pipelined) --------------
template <int MODE>
__global__ void __launch_bounds__(256) k_gemm_mma(const float* __restrict__ x) {
    constexpr int K   = (MODE == 0) ? CC : ICC;
    constexpr int KP  = K / 2;
    constexpr int KPs = (MODE == 0) ? 72 : 136;   // pad: stride % 32 == 8
    constexpr int KS  = K / 16;
    extern __shared__ char smraw[];
    u32* sB = (u32*)smraw;                        // [64][KPs], k-interleaved

    const u16* Ah = (MODE == 0) ? g_kA_h : g_vA_h;
    const u16* Al = (MODE == 0) ? g_kA_l : g_vA_l;
    const u32* src = (MODE == 0) ? g_xs : g_hs;

    int s0 = blockIdx.x * 64, oc0 = blockIdx.y * 128, b = blockIdx.z;
    int tid = threadIdx.x;
    int w = tid >> 5, lane = tid & 31;
    int g = lane >> 2, t = lane & 3;

    float acc[8][4];
#pragma unroll
    for (int nt = 0; nt < 8; ++nt)
#pragma unroll
        for (int q = 0; q < 4; ++q) acc[nt][q] = 0.f;

    for (int i = tid; i < 64 * KP; i += 256) {
        int n = (MODE == 0) ? (i >> 6) : (i >> 7);
        int kp = (MODE == 0) ? (i & 63) : (i & 127);
        sB[n * KPs + kperm(kp)] = src[((size_t)b * HWD + s0 + n) * KP + kp];
    }
    __syncthreads();

    int rowA = oc0 + w * 16 + g;
    const u16* pAh = Ah + (size_t)rowA * K;
    const u16* pAl = Al + (size_t)rowA * K;

    u32 cah[4], cal[4], nah[4], nal[4];
    {
        int kc = t * 2;
        cah[0] = *(const u32*)(pAh + kc);
        cah[1] = *(const u32*)(pAh + (size_t)8 * K + kc);
        cah[2] = *(const u32*)(pAh + kc + 8);
        cah[3] = *(const u32*)(pAh + (size_t)8 * K + kc + 8);
        cal[0] = *(const u32*)(pAl + kc);
        cal[1] = *(const u32*)(pAl + (size_t)8 * K + kc);
        cal[2] = *(const u32*)(pAl + kc + 8);
        cal[3] = *(const u32*)(pAl + (size_t)8 * K + kc + 8);
    }

#pragma unroll
    for (int ks = 0; ks < KS; ++ks) {
        if (ks + 1 < KS) {
            int kc = (ks + 1) * 16 + t * 2;
            nah[0] = *(const u32*)(pAh + kc);
            nah[1] = *(const u32*)(pAh + (size_t)8 * K + kc);
            nah[2] = *(const u32*)(pAh + kc + 8);
            nah[3] = *(const u32*)(pAh + (size_t)8 * K + kc + 8);
            nal[0] = *(const u32*)(pAl + kc);
            nal[1] = *(const u32*)(pAl + (size_t)8 * K + kc);
            nal[2] = *(const u32*)(pAl + kc + 8);
            nal[3] = *(const u32*)(pAl + (size_t)8 * K + kc + 8);
        }
        int kw = ks * 8 + 2 * t;
#pragma unroll
        for (int nt = 0; nt < 8; ++nt) {
            u64 B01 = *(const u64*)&sB[(nt * 8 + g) * KPs + kw];
            u32 b0 = (u32)B01, b1 = (u32)(B01 >> 32);
            mma16816(acc[nt][0], acc[nt][1], acc[nt][2], acc[nt][3],
                     cah[0], cah[1], cah[2], cah[3], b0, b1);
            mma16816(acc[nt][0], acc[nt][1], acc[nt][2], acc[nt][3],
                     cal[0], cal[1], cal[2], cal[3], b0, b1);
        }
#pragma unroll
        for (int q = 0; q < 4; ++q) { cah[q] = nah[q]; cal[q] = nal[q]; }
    }

    if (MODE == 0) {
#pragma unroll
        for (int nt = 0; nt < 8; ++nt) {
            int px = s0 + nt * 8 + t * 2;
            int r0 = rowA, r1 = rowA + 8;
            float k0 = g_kb[r0], k1 = g_kb[r1];
            size_t i0 = ((size_t)b * ICC + r0) * HWD + px;
            size_t i1 = ((size_t)b * ICC + r1) * HWD + px;
            *(float2*)(g_h + i0) = make_float2(acc[nt][0] + k0, acc[nt][1] + k0);
            *(float2*)(g_h + i1) = make_float2(acc[nt][2] + k1, acc[nt][3] + k1);
        }
    } else {
        __syncthreads();                       // done reading sB
        u16* th = (u16*)smraw;                 // [px][128]
        int r0 = rowA, r1 = rowA + 8;
        float iv0 = g_inv2[r0], be0 = g_beta2[r0];
        float iv1 = g_inv2[r1], be1 = g_beta2[r1];
#pragma unroll
        for (int nt = 0; nt < 8; ++nt) {
            int pxl = nt * 8 + t * 2;
            size_t i0 = ((size_t)b * CC + r0) * HWD + s0 + pxl;
            size_t i1 = ((size_t)b * CC + r1) * HWD + s0 + pxl;
            float2 x0 = *(const float2*)(x + i0);
            float2 x1 = *(const float2*)(x + i1);
            float xr00 = acc[nt][0] * HINV + x0.x, xr01 = acc[nt][1] * HINV + x0.y;
            float xr10 = acc[nt][2] * HINV + x1.x, xr11 = acc[nt][3] * HINV + x1.y;
            *(float2*)(g_xr + i0) = make_float2(xr00, xr01);
            *(float2*)(g_xr + i1) = make_float2(xr10, xr11);
            th[pxl * 128 + r0] = f16b(xr00 * iv0 + be0);
            th[(pxl + 1) * 128 + r0] = f16b(xr01 * iv0 + be0);
            th[pxl * 128 + r1] = f16b(xr10 * iv1 + be1);
            th[(pxl + 1) * 128 + r1] = f16b(xr11 * iv1 + be1);
        }
        __syncthreads();
        const u32* th32 = (const u32*)th;
        for (int i = tid; i < 64 * 64; i += 256) {
            int px = i >> 6, cp = i & 63;
            g_nx[((size_t)b * HWD + s0 + px) * 64 + cp] = th32[px * 64 + cp];
        }
    }
}

// ---------------- K2: per-row (b,o) max & sum of exp over 4096 spatial ------
__global__ void k_rowstats() {
    int r = blockIdx.x;
    const float4* p = (const float4*)(g_h + (size_t)r * HWD);
    int t = threadIdx.x;
    float v[16];
#pragma unroll
    for (int k = 0; k < 4; ++k) {
        float4 f = p[t + k * 256];
        v[k * 4 + 0] = f.x; v[k * 4 + 1] = f.y; v[k * 4 + 2] = f.z; v[k * 4 + 3] = f.w;
    }
    float m = v[0];
#pragma unroll
    for (int i = 1; i < 16; ++i) m = fmaxf(m, v[i]);
    __shared__ float red[256];
    red[t] = m; __syncthreads();
    for (int off = 128; off > 0; off >>= 1) {
        if (t < off) red[t] = fmaxf(red[t], red[t + off]);
        __syncthreads();
    }
    float rmax = red[0];
    __syncthreads();
    float s = 0.f;
#pragma unroll
    for (int i = 0; i < 16; ++i) s += __expf(v[i] - rmax);
    red[t] = s; __syncthreads();
    for (int off = 128; off > 0; off >>= 1) {
        if (t < off) red[t] += red[t + off];
        __syncthreads();
    }
    if (t == 0) { g_rowmax[r] = rmax; g_rowsum[r] = red[0]; }
}

// --- K3: softmax + per-head channel-sum norm; write packed fp16 (x256) ------
__global__ void k_dnorm() {
    int s = blockIdx.x * 256 + threadIdx.x;
    int nh = blockIdx.y, b = blockIdx.z;
    __shared__ float smax[32], sinv[32];
    if (threadIdx.x < 32) {
        int rr = b * ICC + nh * 32 + threadIdx.x;
        smax[threadIdx.x] = g_rowmax[rr];
        sinv[threadIdx.x] = 1.0f / g_rowsum[rr];
    }
    __syncthreads();
    float e[32];
    float d = 0.f;
    const float* base = g_h + ((size_t)b * ICC + nh * 32) * HWD + s;
#pragma unroll
    for (int c = 0; c < 32; ++c) {
        float val = __expf(base[(size_t)c * HWD] - smax[c]) * sinv[c];
        e[c] = val; d += val;
    }
    float w = HSCALE / (d + 1e-6f);
    u32* dst = g_hs + ((size_t)b * HWD + s) * (ICC / 2) + nh * 16;
#pragma unroll
    for (int c = 0; c < 32; c += 2)
        dst[c >> 1] = pack2_f16(e[c] * w, e[c + 1] * w);
}

// ------- 3x3 conv: smem weights + raw-halo acts (staged once per chunk) -----
// Block: (y-pair, 128-oc group, b). M=128 oc, N=128 px (2 rows), K=ic*9.
// Acts staged ONCE per 16-ch chunk as [4 rows][66 x][8 icp-words]; the 9-tap
// im2col shift is applied in the mainloop B-address (dy, dx constants).
// For output px (row = px>>6, x = px&63), tap (dy,dx):
//   woff = (row+dy)*RAWROW + (x+dx)*8 + 2t      (halo col 0 <=> x=-1)
// MODE 0: B from g_nx -> bias + GELU -> pack fp16 -> g_tx (channel-last)
// MODE 1: B from g_tx -> bias + g_xr residual -> dout fp32 NCHW
#define WSTR 152                                  // halfwords per oc row (pad)
#define RAWX 66                                   // halo row width in px
#define RAWROW (RAWX * 8)                         // 528 words per raw row
#define RAWSZ (4 * RAWROW)                        // 2112 u32
#define CONV_SMEM (128 * WSTR * 2 + RAWSZ * 4)    // 38912 + 8448 = 47360

template <int MODE>
__global__ void __launch_bounds__(256) k_conv_mma(const float* __restrict__ bias,
                                                  float* __restrict__ dout) {
    constexpr int ICT  = (MODE == 0) ? 128 : 512;
    constexpr int Kt   = ICT * 9;
    constexpr int KPIC = ICT / 2;
    const u32* srcB = (MODE == 0) ? g_nx : g_tx;
    const u16* Wg = (MODE == 0) ? g_w1h : g_w2h;

    extern __shared__ char smraw[];
    u16* sW = (u16*)smraw;                     // [128][WSTR]
    u32* sR = (u32*)(smraw + 128 * WSTR * 2);  // [4][66][8] raw halo acts

    int y0 = blockIdx.x * 2, oc0 = blockIdx.y * 128, b = blockIdx.z;
    int tid = threadIdx.x;
    int w = tid >> 5, lane = tid & 31;
    int g = lane >> 2, t = lane & 3;

    float acc[16][4];
#pragma unroll
    for (int nt = 0; nt < 16; ++nt)
#pragma unroll
        for (int q = 0; q < 4; ++q) acc[nt][q] = 0.f;

    // ldmatrix lane addressing: lanes 0-15 -> rows 0-15 col 0; 16-31 -> col 8
    int rowl = lane & 15, colo = (lane >> 4) * 8;
    u32 aoff = smem_u32(sW) + (u32)(((w * 16 + rowl) * WSTR + colo) * 2);

    const u32* inb = srcB + (size_t)b * HWD * KPIC;
    const u16* gW = Wg + (size_t)oc0 * Kt;

    for (int ci = 0; ci < ICT / 16; ++ci) {
        // stage weights: uint4 copies, [oc][tap][16 ic] -> sW[oc][tap*16..]
        for (int j = tid; j < 128 * 9 * 2; j += 256) {
            int oc = j / 18, r = j - oc * 18, tap = r >> 1, half = r & 1;
            size_t go = (size_t)oc * Kt + tap * ICT + ci * 16 + half * 8;
            *(uint4*)(sW + oc * WSTR + tap * 16 + half * 8) =
                *(const uint4*)(gW + go);
        }
        // stage raw halo acts ONCE: rows y0-1..y0+2, x -1..64, 8 icp words
        for (int i = tid; i < RAWSZ; i += 256) {
            int row = i / RAWROW, rem = i - row * RAWROW;
            int xh = rem >> 3, icp = rem & 7;
            int xx = xh - 1, yy = y0 + row - 1;
            u32 val = 0;
            if ((unsigned)xx < 64u && (unsigned)yy < 64u)
                val = inb[(size_t)(yy * 64 + xx) * KPIC + ci * 8 + icp];
            int pos = (icp < 4) ? (2 * icp) : (2 * (icp - 4) + 1);
            sR[row * RAWROW + xh * 8 + pos] = val;
        }
        __syncthreads();

        u32 ca[4], na[4];
        ldmatrix4(ca, aoff);
#pragma unroll
        for (int ks = 0; ks < 9; ++ks) {
            if (ks + 1 < 9) ldmatrix4(na, aoff + (ks + 1) * 32);
            const int dy = ks / 3, dx = ks - dy * 3;
#pragma unroll
            for (int nt = 0; nt < 16; ++nt) {
                // px = nt*8 + g ; row = nt>>3 ; x = (nt&7)*8 + g
                int woff = ((nt >> 3) + dy) * RAWROW
                         + ((nt & 7) * 8 + g + dx) * 8 + 2 * t;
                u64 B01 = *(const u64*)&sR[woff];
                mma16816(acc[nt][0], acc[nt][1], acc[nt][2], acc[nt][3],
                         ca[0], ca[1], ca[2], ca[3],
                         (u32)B01, (u32)(B01 >> 32));
            }
#pragma unroll
            for (int q = 0; q < 4; ++q) ca[q] = na[q];
        }
        __syncthreads();
    }

    int r0 = oc0 + w * 16 + g, r1 = r0 + 8;
    float b0v = bias[r0], b1v = bias[r1];

    if (MODE == 0) {
        // GELU -> pack fp16 -> smem transpose -> channel-last g_tx
        u16* th = (u16*)smraw;                 // [128 px][128 oc-local]
        int lr0 = r0 - oc0, lr1 = r1 - oc0;
#pragma unroll
        for (int nt = 0; nt < 16; ++nt) {
            int pxl = nt * 8 + t * 2;
            th[pxl * 128 + lr0] = f16b(gelu_exact(acc[nt][0] + b0v));
            th[(pxl + 1) * 128 + lr0] = f16b(gelu_exact(acc[nt][1] + b0v));
            th[pxl * 128 + lr1] = f16b(gelu_exact(acc[nt][2] + b1v));
            th[(pxl + 1) * 128 + lr1] = f16b(gelu_exact(acc[nt][3] + b1v));
        }
        __syncthreads();
        const u32* th32 = (const u32*)th;
        for (int i = tid; i < 128 * 64; i += 256) {
            int px = i >> 6, cp = i & 63;
            g_tx[((size_t)b * HWD + y0 * 64 + px) * (HIDD / 2) + oc0 / 2 + cp] =
                th32[px * 64 + cp];
        }
    } else {
#pragma unroll
        for (int nt = 0; nt < 16; ++nt) {
            int px = nt * 8 + t * 2;
            int s = y0 * 64 + px;
            size_t i0 = ((size_t)b * CC + r0) * HWD + s;
            size_t i1 = ((size_t)b * CC + r1) * HWD + s;
            float2 x0 = *(const float2*)(g_xr + i0);
            float2 x1 = *(const float2*)(g_xr + i1);
            *(float2*)(dout + i0) = make_float2(acc[nt][0] + b0v + x0.x,
                                                acc[nt][1] + b0v + x0.y);
            *(float2*)(dout + i1) = make_float2(acc[nt][2] + b1v + x1.x,
                                                acc[nt][3] + b1v + x1.y);
        }
    }
}

// ---------------------------------------------------------------------------
extern "C" void kernel_launch(void* const* d_in, const int* in_sizes, int n_in,
                              void* d_out, int out_size) {
    (void)in_sizes; (void)n_in; (void)out_size;
    const float* x     = (const float*)d_in[0];
    const float* bn1_g = (const float*)d_in[1];
    const float* bn1_b = (const float*)d_in[2];
    const float* bn1_m = (const float*)d_in[3];
    const float* bn1_v = (const float*)d_in[4];
    const float* kmat  = (const float*)d_in[5];
    const float* vmat  = (const float*)d_in[6];
    const float* bn2_g = (const float*)d_in[7];
    const float* bn2_b = (const float*)d_in[8];
    const float* bn2_m = (const float*)d_in[9];
    const float* bn2_v = (const float*)d_in[10];
    const float* w1    = (const float*)d_in[11];
    const float* b1    = (const float*)d_in[12];
    const float* w2    = (const float*)d_in[13];
    const float* b2    = (const float*)d_in[14];
    float* out = (float*)d_out;

    const int GEMM0_SMEM = 64 * 72 * 4;    // 18432
    const int GEMM1_SMEM = 64 * 136 * 4;   // 34816

    k_fold<<<1, 256>>>(bn1_g, bn1_b, bn1_m, bn1_v, kmat,
                       bn2_g, bn2_b, bn2_m, bn2_v);
    k_prep_w<<<512, 256>>>(w1, w2, vmat);

    dim3 gx(HWD / 64, BB);
    k_xsplit<<<gx, 256>>>(x);

    dim3 g1(HWD / 64, ICC / 128, BB);
    k_gemm_mma<0><<<g1, 256, GEMM0_SMEM>>>(x);

    k_rowstats<<<BB * ICC, 256>>>();

    dim3 gd(HWD / 256, 8, BB);
    k_dnorm<<<gd, 256>>>();

    dim3 g2(HWD / 64, CC / 128, BB);
    k_gemm_mma<1><<<g2, 256, GEMM1_SMEM>>>(x);

    dim3 gc1(32, HIDD / 128, BB);
    k_conv_mma<0><<<gc1, 256, CONV_SMEM>>>(b1, nullptr);

    dim3 gc2(32, CC / 128, BB);
    k_conv_mma<1><<<gc2, 256, CONV_SMEM>>>(b2, out);
}

// round 17
// speedup vs baseline: 2.1869x; 1.1772x over previous
#include <cuda_runtime.h>
#include <cuda_fp16.h>
#include <math.h>

typedef unsigned long long u64;
typedef unsigned int u32;
typedef unsigned short u16;

#define BB   32
#define CC   128
#define ICC  256
#define HWD  4096
#define HIDD 512

#define HSCALE 256.0f
#define HINV   (1.0f / 256.0f)

// ---------------- scratch (static __device__, no allocation) ----------------
__device__ float g_kb[ICC];                    // BN1 bias folded through k
__device__ float g_inv2[CC], g_beta2[CC];      // BN2 folded params
__device__ float g_rowmax[BB * ICC], g_rowsum[BB * ICC];
__device__ float g_h[(size_t)BB * ICC * HWD];  // gemm1 out (pre-softmax), fp32
__device__ float g_xr[(size_t)BB * CC * HWD];  // residual x + attn, fp32

// packed fp16 activation banks, channel-last: one u32 per 2 channels
__device__ __align__(16) u32 g_xs[(size_t)BB * HWD * (CC / 2)];
__device__ __align__(16) u32 g_hs[(size_t)BB * HWD * (ICC / 2)];
__device__ __align__(16) u32 g_nx[(size_t)BB * HWD * (CC / 2)];
__device__ __align__(16) u32 g_tx[(size_t)BB * HWD * (HIDD / 2)];

// fp16 weight planes (single plane everywhere now)
__device__ __align__(16) u16 g_kA[ICC * CC];         // k' [o][c]
__device__ __align__(16) u16 g_vA[CC * ICC];         // v  [c][ic]
__device__ __align__(16) u16 g_w1h[HIDD * CC * 9];   // [oc][tap*128+ic]
__device__ __align__(16) u16 g_w2h[CC * HIDD * 9];   // [oc][tap*512+ic]

// ---------------- helpers ----------------------------------------------------
__device__ __forceinline__ u16 f16b(float v) {
    return __half_as_ushort(__float2half_rn(v));
}
__device__ __forceinline__ u32 pack2_f16(float v0, float v1) {
    return (u32)f16b(v0) | ((u32)f16b(v1) << 16);
}
__device__ __forceinline__ void mma16816(float& c0, float& c1, float& c2, float& c3,
                                         u32 a0, u32 a1, u32 a2, u32 a3,
                                         u32 b0, u32 b1) {
    asm volatile(
        "mma.sync.aligned.m16n8k16.row.col.f32.f16.f16.f32 "
        "{%0,%1,%2,%3},{%4,%5,%6,%7},{%8,%9},{%0,%1,%2,%3};"
        : "+f"(c0), "+f"(c1), "+f"(c2), "+f"(c3)
        : "r"(a0), "r"(a1), "r"(a2), "r"(a3), "r"(b0), "r"(b1));
}
__device__ __forceinline__ void ldmatrix4(u32* r, u32 saddr) {
    asm volatile(
        "ldmatrix.sync.aligned.m8n8.x4.shared.b16 {%0,%1,%2,%3}, [%4];"
        : "=r"(r[0]), "=r"(r[1]), "=r"(r[2]), "=r"(r[3]) : "r"(saddr));
}
__device__ __forceinline__ u32 smem_u32(const void* p) {
    u32 a;
    asm("{ .reg .u64 t; cvta.to.shared.u64 t, %1; cvt.u32.u64 %0, t; }"
        : "=r"(a) : "l"(p));
    return a;
}
__device__ __forceinline__ float gelu_exact(float v) {
    return 0.5f * v * (1.0f + erff(v * 0.70710678118654752f));
}
// interleave permutation within each 8-word k-group: [0,4,1,5,2,6,3,7]
__device__ __forceinline__ int kperm(int kp) {
    int t7 = kp & 7;
    return (kp & ~7) + ((t7 < 4) ? (2 * t7) : (2 * (t7 - 4) + 1));
}

// ---------------- K0: fold BN1 into k (fp16), BN2 params --------------------
__global__ void k_fold(const float* __restrict__ bn1_g, const float* __restrict__ bn1_b,
                       const float* __restrict__ bn1_m, const float* __restrict__ bn1_v,
                       const float* __restrict__ kmat,
                       const float* __restrict__ bn2_g, const float* __restrict__ bn2_b,
                       const float* __restrict__ bn2_m, const float* __restrict__ bn2_v) {
    __shared__ float inv1[CC], beta1[CC];
    int t = threadIdx.x;
    if (t < CC) {
        float iv = bn1_g[t] * rsqrtf(bn1_v[t] + 1e-5f);
        inv1[t] = iv;
        beta1[t] = bn1_b[t] - bn1_m[t] * iv;
        float iv2 = bn2_g[t] * rsqrtf(bn2_v[t] + 1e-6f);
        g_inv2[t] = iv2;
        g_beta2[t] = bn2_b[t] - bn2_m[t] * iv2;
    }
    __syncthreads();
    int o = t;  // 0..255
    float s = 0.f;
    for (int c = 0; c < CC; ++c) {
        float kv = kmat[o * CC + c];
        g_kA[o * CC + c] = f16b(kv * inv1[c]);
        s += kv * beta1[c];
    }
    g_kb[o] = s;
}

// ------- K0b: reorder conv weights to [oc][tap*IC+ic] fp16; v fp16 ----------
__global__ void k_prep_w(const float* __restrict__ w1, const float* __restrict__ w2,
                         const float* __restrict__ vmat) {
    const int n1 = HIDD * CC * 9;
    const int n2 = CC * HIDD * 9;
    const int n3 = CC * ICC;
    int stride = gridDim.x * blockDim.x;
    for (int i = blockIdx.x * blockDim.x + threadIdx.x; i < n1 + n2 + n3; i += stride) {
        if (i < n1) {
            int oc = i / (CC * 9), rem = i - oc * (CC * 9);
            int ic = rem / 9, tap = rem - ic * 9;
            g_w1h[oc * (CC * 9) + tap * CC + ic] = f16b(w1[i]);
        } else if (i < n1 + n2) {
            int q = i - n1;
            int oc = q / (HIDD * 9), rem = q - oc * (HIDD * 9);
            int ic = rem / 9, tap = rem - ic * 9;
            g_w2h[oc * (HIDD * 9) + tap * HIDD + ic] = f16b(w2[q]);
        } else {
            int j = i - n1 - n2;
            g_vA[j] = f16b(vmat[j]);
        }
    }
}

// ------- K0c: x [b][c][s] fp32 -> g_xs [b][s][c/2] packed fp16 --------------
__global__ void k_xsplit(const float* __restrict__ x) {
    __shared__ float sm[CC * 65];   // [c][65] pad
    int s0 = blockIdx.x * 64, b = blockIdx.y;
    int tid = threadIdx.x;
    for (int i = tid; i < CC * 64; i += 256) {
        int c = i >> 6, n = i & 63;
        sm[c * 65 + n] = x[((size_t)b * CC + c) * HWD + s0 + n];
    }
    __syncthreads();
    for (int i = tid; i < 64 * 64; i += 256) {
        int n = i >> 6, cp = i & 63;
        float v0 = sm[(2 * cp) * 65 + n];
        float v1 = sm[(2 * cp + 1) * 65 + n];
        g_xs[((size_t)b * HWD + s0 + n) * 64 + cp] = pack2_f16(v0, v1);
    }
}

// ---------------- 1x1 GEMMs via mma (fp16 single-plane, N=128) --------------
// MODE 0: g_h[b,o,s] = kb[o] + sum_c k'[o,c] x[b,c,s]        (M=256, K=128)
// MODE 1: xr = x + v@h2 -> g_xr fp32 ; g_nx = pack(BN2(xr))  (M=128, K=256)
template <int MODE>
__global__ void __launch_bounds__(256) k_gemm_mma(const float* __restrict__ x) {
    constexpr int K   = (MODE == 0) ? CC : ICC;
    constexpr int KP  = K / 2;
    constexpr int KPs = (MODE == 0) ? 72 : 136;   // pad: stride % 32 == 8
    constexpr int KS  = K / 16;
    extern __shared__ char smraw[];
    u32* sB = (u32*)smraw;                        // [128][KPs], k-interleaved

    const u16* Ah = (MODE == 0) ? g_kA : g_vA;
    const u32* src = (MODE == 0) ? g_xs : g_hs;

    int s0 = blockIdx.x * 128, oc0 = blockIdx.y * 128, b = blockIdx.z;
    int tid = threadIdx.x;
    int w = tid >> 5, lane = tid & 31;
    int g = lane >> 2, t = lane & 3;

    float acc[16][4];
#pragma unroll
    for (int nt = 0; nt < 16; ++nt)
#pragma unroll
        for (int q = 0; q < 4; ++q) acc[nt][q] = 0.f;

    for (int i = tid; i < 128 * KP; i += 256) {
        int n = (MODE == 0) ? (i >> 6) : (i >> 7);
        int kp = (MODE == 0) ? (i & 63) : (i & 127);
        sB[n * KPs + kperm(kp)] = src[((size_t)b * HWD + s0 + n) * KP + kp];
    }
    __syncthreads();

    int rowA = oc0 + w * 16 + g;
    const u16* pA = Ah + (size_t)rowA * K;

    u32 ca[4], na[4];
    {
        int kc = t * 2;
        ca[0] = *(const u32*)(pA + kc);
        ca[1] = *(const u32*)(pA + (size_t)8 * K + kc);
        ca[2] = *(const u32*)(pA + kc + 8);
        ca[3] = *(const u32*)(pA + (size_t)8 * K + kc + 8);
    }

#pragma unroll
    for (int ks = 0; ks < KS; ++ks) {
        if (ks + 1 < KS) {
            int kc = (ks + 1) * 16 + t * 2;
            na[0] = *(const u32*)(pA + kc);
            na[1] = *(const u32*)(pA + (size_t)8 * K + kc);
            na[2] = *(const u32*)(pA + kc + 8);
            na[3] = *(const u32*)(pA + (size_t)8 * K + kc + 8);
        }
        int kw = ks * 8 + 2 * t;
#pragma unroll
        for (int nt = 0; nt < 16; ++nt) {
            u64 B01 = *(const u64*)&sB[(nt * 8 + g) * KPs + kw];
            mma16816(acc[nt][0], acc[nt][1], acc[nt][2], acc[nt][3],
                     ca[0], ca[1], ca[2], ca[3],
                     (u32)B01, (u32)(B01 >> 32));
        }
#pragma unroll
        for (int q = 0; q < 4; ++q) ca[q] = na[q];
    }

    if (MODE == 0) {
#pragma unroll
        for (int nt = 0; nt < 16; ++nt) {
            int px = s0 + nt * 8 + t * 2;
            int r0 = rowA, r1 = rowA + 8;
            float k0 = g_kb[r0], k1 = g_kb[r1];
            size_t i0 = ((size_t)b * ICC + r0) * HWD + px;
            size_t i1 = ((size_t)b * ICC + r1) * HWD + px;
            *(float2*)(g_h + i0) = make_float2(acc[nt][0] + k0, acc[nt][1] + k0);
            *(float2*)(g_h + i1) = make_float2(acc[nt][2] + k1, acc[nt][3] + k1);
        }
    } else {
        // h2 was scaled by 256 -> unscale; fp32 residual + packed BN2 out
        __syncthreads();                       // done reading sB
        u16* th = (u16*)smraw;                 // [128 px][128 c]
        int r0 = rowA, r1 = rowA + 8;
        float iv0 = g_inv2[r0], be0 = g_beta2[r0];
        float iv1 = g_inv2[r1], be1 = g_beta2[r1];
#pragma unroll
        for (int nt = 0; nt < 16; ++nt) {
            int pxl = nt * 8 + t * 2;
            size_t i0 = ((size_t)b * CC + r0) * HWD + s0 + pxl;
            size_t i1 = ((size_t)b * CC + r1) * HWD + s0 + pxl;
            float2 x0 = *(const float2*)(x + i0);
            float2 x1 = *(const float2*)(x + i1);
            float xr00 = acc[nt][0] * HINV + x0.x, xr01 = acc[nt][1] * HINV + x0.y;
            float xr10 = acc[nt][2] * HINV + x1.x, xr11 = acc[nt][3] * HINV + x1.y;
            *(float2*)(g_xr + i0) = make_float2(xr00, xr01);
            *(float2*)(g_xr + i1) = make_float2(xr10, xr11);
            th[pxl * 128 + r0] = f16b(xr00 * iv0 + be0);
            th[(pxl + 1) * 128 + r0] = f16b(xr01 * iv0 + be0);
            th[pxl * 128 + r1] = f16b(xr10 * iv1 + be1);
            th[(pxl + 1) * 128 + r1] = f16b(xr11 * iv1 + be1);
        }
        __syncthreads();
        const u32* th32 = (const u32*)th;
        for (int i = tid; i < 128 * 64; i += 256) {
            int px = i >> 6, cp = i & 63;
            g_nx[((size_t)b * HWD + s0 + px) * 64 + cp] = th32[px * 64 + cp];
        }
    }
}

// ---------------- K2: per-row (b,o) max & sum of exp over 4096 spatial ------
__global__ void k_rowstats() {
    int r = blockIdx.x;
    const float4* p = (const float4*)(g_h + (size_t)r * HWD);
    int t = threadIdx.x;
    float v[16];
#pragma unroll
    for (int k = 0; k < 4; ++k) {
        float4 f = p[t + k * 256];
        v[k * 4 + 0] = f.x; v[k * 4 + 1] = f.y; v[k * 4 + 2] = f.z; v[k * 4 + 3] = f.w;
    }
    float m = v[0];
#pragma unroll
    for (int i = 1; i < 16; ++i) m = fmaxf(m, v[i]);
    __shared__ float red[256];
    red[t] = m; __syncthreads();
    for (int off = 128; off > 0; off >>= 1) {
        if (t < off) red[t] = fmaxf(red[t], red[t + off]);
        __syncthreads();
    }
    float rmax = red[0];
    __syncthreads();
    float s = 0.f;
#pragma unroll
    for (int i = 0; i < 16; ++i) s += __expf(v[i] - rmax);
    red[t] = s; __syncthreads();
    for (int off = 128; off > 0; off >>= 1) {
        if (t < off) red[t] += red[t + off];
        __syncthreads();
    }
    if (t == 0) { g_rowmax[r] = rmax; g_rowsum[r] = red[0]; }
}

// --- K3: softmax + per-head channel-sum norm; write packed fp16 (x256) ------
__global__ void k_dnorm() {
    int s = blockIdx.x * 256 + threadIdx.x;
    int nh = blockIdx.y, b = blockIdx.z;
    __shared__ float smax[32], sinv[32];
    if (threadIdx.x < 32) {
        int rr = b * ICC + nh * 32 + threadIdx.x;
        smax[threadIdx.x] = g_rowmax[rr];
        sinv[threadIdx.x] = 1.0f / g_rowsum[rr];
    }
    __syncthreads();
    float e[32];
    float d = 0.f;
    const float* base = g_h + ((size_t)b * ICC + nh * 32) * HWD + s;
#pragma unroll
    for (int c = 0; c < 32; ++c) {
        float val = __expf(base[(size_t)c * HWD] - smax[c]) * sinv[c];
        e[c] = val; d += val;
    }
    float w = HSCALE / (d + 1e-6f);
    u32* dst = g_hs + ((size_t)b * HWD + s) * (ICC / 2) + nh * 16;
#pragma unroll
    for (int c = 0; c < 32; c += 2)
        dst[c >> 1] = pack2_f16(e[c] * w, e[c + 1] * w);
}

// ------- 3x3 conv: smem weights + raw halo, 4-row (256 px) tiles ------------
// Block: (y-quad, 128-oc group, b). M=128 oc, N=256 px (4 rows), K=ic*9.
// Acts staged ONCE per 16-ch chunk as [6 rows][66 x][8 icp-words]; tap shift
// applied in the mainloop B-address:
//   px = nt*8+g ; row = nt>>3 ; x = (nt&7)*8+g
//   woff = (row+dy)*RAWROW + (x+dx)*8 + 2t      (halo col 0 <=> x=-1)
// MODE 0: B from g_nx -> bias + GELU -> pack fp16 -> g_tx (channel-last)
// MODE 1: B from g_tx -> bias + g_xr residual -> dout fp32 NCHW
#define WSTR 152                                  // halfwords per oc row (pad)
#define RAWX 66                                   // halo row width in px
#define RAWROW (RAWX * 8)                         // 528 words per raw row
#define RAWSZ (6 * RAWROW)                        // 3168 u32
#define CONV_SMEM (128 * WSTR * 2 + RAWSZ * 4)    // 38912 + 12672 = 51584

template <int MODE>
__global__ void __launch_bounds__(256) k_conv_mma(const float* __restrict__ bias,
                                                  float* __restrict__ dout) {
    constexpr int ICT  = (MODE == 0) ? 128 : 512;
    constexpr int Kt   = ICT * 9;
    constexpr int KPIC = ICT / 2;
    const u32* srcB = (MODE == 0) ? g_nx : g_tx;
    const u16* Wg = (MODE == 0) ? g_w1h : g_w2h;

    extern __shared__ char smraw[];
    u16* sW = (u16*)smraw;                     // [128][WSTR]
    u32* sR = (u32*)(smraw + 128 * WSTR * 2);  // [6][66][8] raw halo acts

    int y0 = blockIdx.x * 4, oc0 = blockIdx.y * 128, b = blockIdx.z;
    int tid = threadIdx.x;
    int w = tid >> 5, lane = tid & 31;
    int g = lane >> 2, t = lane & 3;

    float acc[32][4];
#pragma unroll
    for (int nt = 0; nt < 32; ++nt)
#pragma unroll
        for (int q = 0; q < 4; ++q) acc[nt][q] = 0.f;

    // ldmatrix lane addressing: lanes 0-15 -> rows 0-15 col 0; 16-31 -> col 8
    int rowl = lane & 15, colo = (lane >> 4) * 8;
    u32 aoff = smem_u32(sW) + (u32)(((w * 16 + rowl) * WSTR + colo) * 2);

    const u32* inb = srcB + (size_t)b * HWD * KPIC;
    const u16* gW = Wg + (size_t)oc0 * Kt;

    for (int ci = 0; ci < ICT / 16; ++ci) {
        // stage weights: uint4 copies, [oc][tap][16 ic] -> sW[oc][tap*16..]
        for (int j = tid; j < 128 * 9 * 2; j += 256) {
            int oc = j / 18, r = j - oc * 18, tap = r >> 1, half = r & 1;
            size_t go = (size_t)oc * Kt + tap * ICT + ci * 16 + half * 8;
            *(uint4*)(sW + oc * WSTR + tap * 16 + half * 8) =
                *(const uint4*)(gW + go);
        }
        // stage raw halo acts ONCE: rows y0-1..y0+4, x -1..64, 8 icp words
        for (int i = tid; i < RAWSZ; i += 256) {
            int row = i / RAWROW, rem = i - row * RAWROW;
            int xh = rem >> 3, icp = rem & 7;
            int xx = xh - 1, yy = y0 + row - 1;
            u32 val = 0;
            if ((unsigned)xx < 64u && (unsigned)yy < 64u)
                val = inb[(size_t)(yy * 64 + xx) * KPIC + ci * 8 + icp];
            int pos = (icp < 4) ? (2 * icp) : (2 * (icp - 4) + 1);
            sR[row * RAWROW + xh * 8 + pos] = val;
        }
        __syncthreads();

        u32 ca[4], na[4];
        ldmatrix4(ca, aoff);
#pragma unroll
        for (int ks = 0; ks < 9; ++ks) {
            if (ks + 1 < 9) ldmatrix4(na, aoff + (ks + 1) * 32);
            const int dy = ks / 3, dx = ks - dy * 3;
#pragma unroll
            for (int nt = 0; nt < 32; ++nt) {
                int woff = ((nt >> 3) + dy) * RAWROW
                         + ((nt & 7) * 8 + g + dx) * 8 + 2 * t;
                u64 B01 = *(const u64*)&sR[woff];
                mma16816(acc[nt][0], acc[nt][1], acc[nt][2], acc[nt][3],
                         ca[0], ca[1], ca[2], ca[3],
                         (u32)B01, (u32)(B01 >> 32));
            }
#pragma unroll
            for (int q = 0; q < 4; ++q) ca[q] = na[q];
        }
        __syncthreads();
    }

    int r0 = oc0 + w * 16 + g, r1 = r0 + 8;
    float b0v = bias[r0], b1v = bias[r1];

    if (MODE == 0) {
        // GELU -> pack fp16 -> smem transpose (two 128-px halves) -> g_tx
        u16* th = (u16*)smraw;                 // [128 px][128 oc-local]
        const u32* th32 = (const u32*)th;
        int lr0 = r0 - oc0, lr1 = r1 - oc0;
#pragma unroll
        for (int half = 0; half < 2; ++half) {
            if (half) __syncthreads();
#pragma unroll
            for (int nn = 0; nn < 16; ++nn) {
                int nt = half * 16 + nn;
                int pxl = nn * 8 + t * 2;
                th[pxl * 128 + lr0] = f16b(gelu_exact(acc[nt][0] + b0v));
                th[(pxl + 1) * 128 + lr0] = f16b(gelu_exact(acc[nt][1] + b0v));
                th[pxl * 128 + lr1] = f16b(gelu_exact(acc[nt][2] + b1v));
                th[(pxl + 1) * 128 + lr1] = f16b(gelu_exact(acc[nt][3] + b1v));
            }
            __syncthreads();
            for (int i = tid; i < 128 * 64; i += 256) {
                int px = i >> 6, cp = i & 63;
                int pxg = half * 128 + px;
                g_tx[((size_t)b * HWD + y0 * 64 + pxg) * (HIDD / 2) + oc0 / 2 + cp] =
                    th32[px * 64 + cp];
            }
        }
    } else {
#pragma unroll
        for (int nt = 0; nt < 32; ++nt) {
            int px = nt * 8 + t * 2;
            int s = y0 * 64 + px;
            size_t i0 = ((size_t)b * CC + r0) * HWD + s;
            size_t i1 = ((size_t)b * CC + r1) * HWD + s;
            float2 x0 = *(const float2*)(g_xr + i0);
            float2 x1 = *(const float2*)(g_xr + i1);
            *(float2*)(dout + i0) = make_float2(acc[nt][0] + b0v + x0.x,
                                                acc[nt][1] + b0v + x0.y);
            *(float2*)(dout + i1) = make_float2(acc[nt][2] + b1v + x1.x,
                                                acc[nt][3] + b1v + x1.y);
        }
    }
}

// ---------------------------------------------------------------------------
extern "C" void kernel_launch(void* const* d_in, const int* in_sizes, int n_in,
                              void* d_out, int out_size) {
    (void)in_sizes; (void)n_in; (void)out_size;
    const float* x     = (const float*)d_in[0];
    const float* bn1_g = (const float*)d_in[1];
    const float* bn1_b = (const float*)d_in[2];
    const float* bn1_m = (const float*)d_in[3];
    const float* bn1_v = (const float*)d_in[4];
    const float* kmat  = (const float*)d_in[5];
    const float* vmat  = (const float*)d_in[6];
    const float* bn2_g = (const float*)d_in[7];
    const float* bn2_b = (const float*)d_in[8];
    const float* bn2_m = (const float*)d_in[9];
    const float* bn2_v = (const float*)d_in[10];
    const float* w1    = (const float*)d_in[11];
    const float* b1    = (const float*)d_in[12];
    const float* w2    = (const float*)d_in[13];
    const float* b2    = (const float*)d_in[14];
    float* out = (float*)d_out;

    const int GEMM0_SMEM = 128 * 72 * 4;    // 36864
    const int GEMM1_SMEM = 128 * 136 * 4;   // 69632

    static bool attr_done = false;
    if (!attr_done) {
        cudaFuncSetAttribute(k_gemm_mma<1>, cudaFuncAttributeMaxDynamicSharedMemorySize, GEMM1_SMEM);
        cudaFuncSetAttribute(k_conv_mma<0>, cudaFuncAttributeMaxDynamicSharedMemorySize, CONV_SMEM);
        cudaFuncSetAttribute(k_conv_mma<1>, cudaFuncAttributeMaxDynamicSharedMemorySize, CONV_SMEM);
        attr_done = true;
    }

    k_fold<<<1, 256>>>(bn1_g, bn1_b, bn1_m, bn1_v, kmat,
                       bn2_g, bn2_b, bn2_m, bn2_v);
    k_prep_w<<<512, 256>>>(w1, w2, vmat);

    dim3 gx(HWD / 64, BB);
    k_xsplit<<<gx, 256>>>(x);

    dim3 g1(HWD / 128, ICC / 128, BB);
    k_gemm_mma<0><<<g1, 256, GEMM0_SMEM>>>(x);

    k_rowstats<<<BB * ICC, 256>>>();

    dim3 gd(HWD / 256, 8, BB);
    k_dnorm<<<gd, 256>>>();

    dim3 g2(HWD / 128, CC / 128, BB);
    k_gemm_mma<1><<<g2, 256, GEMM1_SMEM>>>(x);

    dim3 gc1(16, HIDD / 128, BB);
    k_conv_mma<0><<<gc1, 256, CONV_SMEM>>>(b1, nullptr);

    dim3 gc2(16, CC / 128, BB);
    k_conv_mma<1><<<gc2, 256, CONV_SMEM>>>(b2, out);
}